// round 1
// baseline (speedup 1.0000x reference)
#include <cuda_runtime.h>
#include <math.h>
#include <stdint.h>

// Problem dims
#define BB 1024
#define HH 256
#define II 32
#define LL 128
#define ZZ 128

#define NBLK 128
#define NTHR 256

// ---------------- device scratch (static allocation is the sanctioned path) ----
__device__ float g_t0[BB * 512];
__device__ float g_t1[BB * 512];
__device__ float g_h[2][BB * HH];     // decode hidden ping-pong
__device__ float g_c[BB * HH];        // decode cell init (then register-resident)
__device__ float g_x0[BB * HH];
__device__ float g_hp[2][BB * II];    // predictor hidden ping-pong
__device__ float g_y[BB * LL * II];   // predictor outputs (pre softmax/sigmoid)
__device__ float g_rWsum[1024 * 256]; // rWih + rWhh
__device__ float g_rb[1024];          // rbih + rbhh
__device__ float g_pb[128];           // pbih + pbhh
__device__ unsigned g_count = 0;
__device__ unsigned g_gen = 0;

// ---------------- smem layout of the persistent kernel (floats) ---------------
#define WD_STRIDE 257
#define WP_STRIDE 289
#define OFF_WD   0
#define OFF_WP   (OFF_WD + 128 * WD_STRIDE)   // 32896
#define OFF_AS   (OFF_WP + 32 * WP_STRIDE)    // + 9248
#define OFF_ASP  (OFF_AS + 64 * 33)           // + 2112
#define OFF_WS0  (OFF_ASP + 32 * 33)          // + 1056
#define SMEM_FLOATS (OFF_WS0 + 128 * 33)      // + 4224  => 49536 floats
#define SMEM_BYTES  (SMEM_FLOATS * 4)         // 198144 bytes < 227KB

__device__ __forceinline__ float sigm(float x) { return 1.f / (1.f + expf(-x)); }

// Grid-wide barrier (CG-style software path): fence -> arrive -> spin -> fence.
__device__ __forceinline__ void grid_sync() {
    __syncthreads();
    if (threadIdx.x == 0) {
        volatile unsigned* genp = &g_gen;
        unsigned gen = *genp;
        __threadfence();
        unsigned prev = atomicAdd(&g_count, 1u);
        if (prev == NBLK - 1) {
            g_count = 0;
            __threadfence();
            *genp = gen + 1;
        } else {
            while (*genp == gen) { __nanosleep(64); }
            __threadfence();
        }
    }
    __syncthreads();
}

// one 32-wide K-chunk of the decode GEMM micro-tile (4 rows x 8 cols / thread)
template <int WSTRIDE>
__device__ __forceinline__ void dec_chunk_compute(float acc[4][8], const float* __restrict__ As,
                                                  const float* __restrict__ W, int wcol0,
                                                  int tx, int ty) {
    const float* ap = As + ty * 4 * 33;
#pragma unroll
    for (int k = 0; k < 32; ++k) {
        float a0 = ap[0 * 33 + k];
        float a1 = ap[1 * 33 + k];
        float a2 = ap[2 * 33 + k];
        float a3 = ap[3 * 33 + k];
#pragma unroll
        for (int j = 0; j < 8; ++j) {
            float w = W[(tx + 16 * j) * WSTRIDE + wcol0 + k];
            acc[0][j] = fmaf(a0, w, acc[0][j]);
            acc[1][j] = fmaf(a1, w, acc[1][j]);
            acc[2][j] = fmaf(a2, w, acc[2][j]);
            acc[3][j] = fmaf(a3, w, acc[3][j]);
        }
    }
}

// ---------------- persistent decode + predictor kernel -------------------------
__global__ void __launch_bounds__(NTHR, 1)
decode_kernel(const float* __restrict__ rWih, const float* __restrict__ rWhh,
              const float* __restrict__ pWih, const float* __restrict__ pWhh) {
    extern __shared__ float sm[];
    float* Wd  = sm + OFF_WD;   // [128][257] decode weight slice (rWsum rows)
    float* Wp  = sm + OFF_WP;   // [32][289]  predictor weight slice (K=288)
    float* As  = sm + OFF_AS;   // [64][33]   decode A chunk
    float* Asp = sm + OFF_ASP;  // [32][33]   predictor A chunk
    float* Ws0 = sm + OFF_WS0;  // [128][33]  step-0 weight staging
    __shared__ float biasD[128];
    __shared__ float biasP[32];

    const int bid = blockIdx.x;
    const int tid = threadIdx.x;
    const int tx = tid & 15, ty = tid >> 4;
    // decode role: 16 M-tiles(64) x 8 H-tiles(32)
    const int dec_mt = bid >> 3, dec_ht = bid & 7;
    // predictor role: 32 M-tiles(32) x 4 I-tiles(8)
    const int pm = bid >> 2, pic = bid & 3;
    const int pr = tid >> 3, picl = tid & 7;

    // ---- one-time preloads (weights resident in SMEM for all 128 steps) ----
    for (int e = tid; e < 128 * 256; e += NTHR) {
        int c = e >> 8, k = e & 255;
        int grow = (c >> 5) * 256 + dec_ht * 32 + (c & 31);
        Wd[c * WD_STRIDE + k] = g_rWsum[grow * 256 + k];
    }
    for (int c = 0; c < 32; ++c) {
        int g = c >> 3, ic = c & 7;
        int prow = g * 32 + pic * 8 + ic;
        for (int k = tid; k < 288; k += NTHR) {
            float v = (k < 256) ? pWih[prow * 256 + k] : pWhh[prow * 32 + (k - 256)];
            Wp[c * WP_STRIDE + k] = v;
        }
    }
    if (tid < 128) {
        int c = tid;
        biasD[c] = g_rb[(c >> 5) * 256 + dec_ht * 32 + (c & 31)];
    }
    if (tid < 32) {
        int c = tid;
        biasP[c] = g_pb[(c >> 3) * 32 + pic * 8 + (c & 7)];
    }
    // decode cell state, register-resident for all steps (this block owns its tile)
    float creg[4][2];
#pragma unroll
    for (int i = 0; i < 4; ++i) {
        int m = dec_mt * 64 + ty * 4 + i;
        creg[i][0] = g_c[m * 256 + dec_ht * 32 + tx];
        creg[i][1] = g_c[m * 256 + dec_ht * 32 + tx + 16];
    }
    float cp_reg = 0.f; // predictor cell state (thread owns one (m, icol))
    __syncthreads();

    for (int t = 0; t < LL; ++t) {
        const int ib = t & 1, ob = ib ^ 1;

        // ================= decode LSTM step t =================
        float acc[4][8];
#pragma unroll
        for (int i = 0; i < 4; ++i)
#pragma unroll
            for (int j = 0; j < 8; ++j) acc[i][j] = biasD[tx + 16 * j];

        if (t == 0) {
            // gates = x0 @ rWih^T + h0 @ rWhh^T  (K=256 each, weights from global)
#pragma unroll 1
            for (int pass = 0; pass < 2; ++pass) {
                const float* Ab = (pass == 0 ? g_x0 : g_h[0]) + dec_mt * 64 * 256;
                const float* Wsrc = (pass == 0 ? rWih : rWhh);
                for (int kk = 0; kk < 256; kk += 32) {
#pragma unroll
                    for (int e = tid; e < 2048; e += NTHR) {
                        int m = e >> 5, k = e & 31;
                        As[m * 33 + k] = __ldcg(Ab + m * 256 + kk + k);
                    }
#pragma unroll
                    for (int e = tid; e < 4096; e += NTHR) {
                        int c = e >> 5, k = e & 31;
                        int grow = (c >> 5) * 256 + dec_ht * 32 + (c & 31);
                        Ws0[c * 33 + k] = Wsrc[grow * 256 + kk + k];
                    }
                    __syncthreads();
                    dec_chunk_compute<33>(acc, As, Ws0, 0, tx, ty);
                    __syncthreads();
                }
            }
        } else {
            // steps >= 1: tok == h_prev  =>  gates = h_prev @ (rWih+rWhh)^T, K=256
            const float* Ab = g_h[ib] + dec_mt * 64 * 256;
            for (int kk = 0; kk < 256; kk += 32) {
#pragma unroll
                for (int e = tid; e < 2048; e += NTHR) {
                    int m = e >> 5, k = e & 31;
                    As[m * 33 + k] = __ldcg(Ab + m * 256 + kk + k);
                }
                __syncthreads();
                dec_chunk_compute<WD_STRIDE>(acc, As, Wd, kk, tx, ty);
                __syncthreads();
            }
        }

        // cell update: thread holds full (i,f,g,o) quads for hcols tx and tx+16
#pragma unroll
        for (int i = 0; i < 4; ++i) {
            int m = dec_mt * 64 + ty * 4 + i;
            {
                float ig = sigm(acc[i][0]), fg = sigm(acc[i][2]);
                float gg = tanhf(acc[i][4]), og = sigm(acc[i][6]);
                float cn = fg * creg[i][0] + ig * gg;
                creg[i][0] = cn;
                g_h[ob][m * 256 + dec_ht * 32 + tx] = og * tanhf(cn);
            }
            {
                float ig = sigm(acc[i][1]), fg = sigm(acc[i][3]);
                float gg = tanhf(acc[i][5]), og = sigm(acc[i][7]);
                float cn = fg * creg[i][1] + ig * gg;
                creg[i][1] = cn;
                g_h[ob][m * 256 + dec_ht * 32 + tx + 16] = og * tanhf(cn);
            }
        }

        grid_sync(); // publishes h[ob]; the single barrier per step (see ping-pong proof)

        // ================= predictor LSTM step t (xt = h[ob]) =================
        float pa[4];
#pragma unroll
        for (int g = 0; g < 4; ++g) pa[g] = biasP[g * 8 + picl];

        const float* Xb = g_h[ob] + pm * 32 * 256;
        for (int kk = 0; kk < 9; ++kk) {
            if (kk < 8) {
#pragma unroll
                for (int e = tid; e < 1024; e += NTHR) {
                    int rr = e >> 5, k = e & 31;
                    Asp[rr * 33 + k] = __ldcg(Xb + rr * 256 + kk * 32 + k);
                }
            } else {
#pragma unroll
                for (int e = tid; e < 1024; e += NTHR) {
                    int rr = e >> 5, k = e & 31;
                    Asp[rr * 33 + k] = __ldcg(&g_hp[ib][(pm * 32 + rr) * 32 + k]);
                }
            }
            __syncthreads();
#pragma unroll
            for (int k = 0; k < 32; ++k) {
                float a = Asp[pr * 33 + k];
#pragma unroll
                for (int g = 0; g < 4; ++g)
                    pa[g] = fmaf(a, Wp[(g * 8 + picl) * WP_STRIDE + kk * 32 + k], pa[g]);
            }
            __syncthreads();
        }
        {
            float ig = sigm(pa[0]), fg = sigm(pa[1]);
            float gg = tanhf(pa[2]), og = sigm(pa[3]);
            float cn = fg * cp_reg + ig * gg;
            cp_reg = cn;
            float hn = og * tanhf(cn);
            int m = pm * 32 + pr, icol = pic * 8 + picl;
            g_hp[ob][m * 32 + icol] = hn;
            g_y[(m * LL + t) * II + icol] = hn;
        }
    }
}

// ---------------- generic fused GEMM for the MLP front: C = act(A @ W^T + b) ---
__device__ __forceinline__ float* buf_ptr(int id) {
    switch (id) {
        case 0: return g_t0;
        case 1: return g_t1;
        case 2: return g_h[0];
        case 3: return g_c;
        case 4: return g_x0;
    }
    return nullptr;
}

__global__ void __launch_bounds__(256)
gemm_kernel(const float* __restrict__ Aext, int a_id,
            const float* __restrict__ W, const float* __restrict__ bias,
            int c_id, int M, int N, int K, int act) {
    __shared__ float As[64 * 33];
    __shared__ float Ws[64 * 33];
    const float* A = Aext ? Aext : buf_ptr(a_id);
    float* C = buf_ptr(c_id);
    int tid = threadIdx.x, tx = tid & 15, ty = tid >> 4;
    int m0 = blockIdx.y * 64, n0 = blockIdx.x * 64;
    float acc[4][4] = {};
    for (int kk = 0; kk < K; kk += 32) {
#pragma unroll
        for (int e = tid; e < 2048; e += 256) {
            int r = e >> 5, k = e & 31;
            As[r * 33 + k] = A[(m0 + r) * K + kk + k];
            Ws[r * 33 + k] = W[(n0 + r) * K + kk + k];
        }
        __syncthreads();
#pragma unroll
        for (int k = 0; k < 32; ++k) {
            float a[4], w[4];
#pragma unroll
            for (int i = 0; i < 4; ++i) a[i] = As[(ty * 4 + i) * 33 + k];
#pragma unroll
            for (int j = 0; j < 4; ++j) w[j] = Ws[(tx + 16 * j) * 33 + k];
#pragma unroll
            for (int i = 0; i < 4; ++i)
#pragma unroll
                for (int j = 0; j < 4; ++j) acc[i][j] = fmaf(a[i], w[j], acc[i][j]);
        }
        __syncthreads();
    }
#pragma unroll
    for (int i = 0; i < 4; ++i)
#pragma unroll
        for (int j = 0; j < 4; ++j) {
            int n = n0 + tx + 16 * j;
            float v = acc[i][j] + bias[n];
            if (act) v = (v >= 0.f) ? v : 0.2f * v;
            C[(m0 + ty * 4 + i) * N + n] = v;
        }
}

// ---------------- init: weight sums, bias sums, zero predictor state ----------
__global__ void init_kernel(const float* __restrict__ rWih, const float* __restrict__ rWhh,
                            const float* __restrict__ rbih, const float* __restrict__ rbhh,
                            const float* __restrict__ pbih, const float* __restrict__ pbhh) {
    int i = blockIdx.x * blockDim.x + threadIdx.x;
    if (i < 1024 * 256) g_rWsum[i] = rWih[i] + rWhh[i];
    if (i < 1024) g_rb[i] = rbih[i] + rbhh[i];
    if (i < 128) g_pb[i] = pbih[i] + pbhh[i];
    if (i < BB * II) { g_hp[0][i] = 0.f; g_hp[1][i] = 0.f; }
}

// ---------------- epilogue: softmax over 31 channels + sigmoid on last --------
__global__ void __launch_bounds__(256)
out_kernel(float* __restrict__ out) {
    int gw = (blockIdx.x * blockDim.x + threadIdx.x) >> 5;
    int lane = threadIdx.x & 31;
    if (gw >= BB * LL) return;
    float v = g_y[gw * 32 + lane];
    float sv = (lane < 31) ? v : -3.0e38f;
    float mx = sv;
#pragma unroll
    for (int o = 16; o; o >>= 1) mx = fmaxf(mx, __shfl_xor_sync(0xffffffffu, mx, o));
    float e = (lane < 31) ? expf(sv - mx) : 0.f;
    float s = e;
#pragma unroll
    for (int o = 16; o; o >>= 1) s += __shfl_xor_sync(0xffffffffu, s, o);
    float r = (lane < 31) ? (e / s) : (1.f / (1.f + expf(-v)));
    out[gw * 32 + lane] = r;
}

// ---------------- launcher ----------------------------------------------------
extern "C" void kernel_launch(void* const* d_in, const int* in_sizes, int n_in,
                              void* d_out, int out_size) {
    const float* x    = (const float*)d_in[0];
    const float* W1   = (const float*)d_in[1];  const float* b1  = (const float*)d_in[2];
    const float* W2   = (const float*)d_in[3];  const float* b2  = (const float*)d_in[4];
    const float* W3   = (const float*)d_in[5];  const float* b3  = (const float*)d_in[6];
    const float* Wh1  = (const float*)d_in[7];  const float* bh1 = (const float*)d_in[8];
    const float* Wh2  = (const float*)d_in[9];  const float* bh2 = (const float*)d_in[10];
    const float* Wc1  = (const float*)d_in[11]; const float* bc1 = (const float*)d_in[12];
    const float* Wc2  = (const float*)d_in[13]; const float* bc2 = (const float*)d_in[14];
    const float* Wx1  = (const float*)d_in[15]; const float* bx1 = (const float*)d_in[16];
    const float* Wx2  = (const float*)d_in[17]; const float* bx2 = (const float*)d_in[18];
    const float* rWih = (const float*)d_in[19]; const float* rWhh = (const float*)d_in[20];
    const float* rbih = (const float*)d_in[21]; const float* rbhh = (const float*)d_in[22];
    const float* pWih = (const float*)d_in[23]; const float* pWhh = (const float*)d_in[24];
    const float* pbih = (const float*)d_in[25]; const float* pbhh = (const float*)d_in[26];
    float* out = (float*)d_out;

    cudaFuncSetAttribute(decode_kernel, cudaFuncAttributeMaxDynamicSharedMemorySize, SMEM_BYTES);

    init_kernel<<<1024, 256>>>(rWih, rWhh, rbih, rbhh, pbih, pbhh);

    // MLP front: buf ids: 0=g_t0, 1=g_t1, 2=g_h[0], 3=g_c, 4=g_x0
    dim3 blk(256);
    gemm_kernel<<<dim3(8, 16), blk>>>(x,    -1, W1,  b1,  1, BB, 512, 128, 1);
    gemm_kernel<<<dim3(8, 16), blk>>>(NULL,  1, W2,  b2,  0, BB, 512, 512, 1);
    gemm_kernel<<<dim3(8, 16), blk>>>(NULL,  0, W3,  b3,  1, BB, 512, 512, 1); // t3 -> g_t1
    gemm_kernel<<<dim3(8, 16), blk>>>(NULL,  1, Wh1, bh1, 0, BB, 512, 512, 1);
    gemm_kernel<<<dim3(4, 16), blk>>>(NULL,  0, Wh2, bh2, 2, BB, 256, 512, 0); // h init
    gemm_kernel<<<dim3(8, 16), blk>>>(NULL,  1, Wc1, bc1, 0, BB, 512, 512, 1);
    gemm_kernel<<<dim3(4, 16), blk>>>(NULL,  0, Wc2, bc2, 3, BB, 256, 512, 0); // c init
    gemm_kernel<<<dim3(8, 16), blk>>>(NULL,  1, Wx1, bx1, 0, BB, 512, 512, 1);
    gemm_kernel<<<dim3(4, 16), blk>>>(NULL,  0, Wx2, bx2, 4, BB, 256, 512, 0); // x0

    decode_kernel<<<NBLK, NTHR, SMEM_BYTES>>>(rWih, rWhh, pWih, pWhh);

    out_kernel<<<(BB * LL) / 8, 256>>>(out);
}

// round 6
// speedup vs baseline: 2.2360x; 2.2360x over previous
#include <cuda_runtime.h>
#include <math.h>
#include <stdint.h>

// Problem dims
#define BB 1024
#define HH 256
#define II 32
#define LL 128

#define NBLK 128
#define NTHR 256

// ---------------- device scratch ----------------------------------------------
__device__ float g_t0[BB * 512];
__device__ float g_t1[BB * 512];
__device__ float g_h[2][BB * HH];     // decode hidden ping-pong (tf32-rounded values)
__device__ float g_c[BB * HH];        // decode cell init
__device__ float g_x0[BB * HH];
__device__ float g_hp[2][BB * II];    // predictor hidden ping-pong (tf32-rounded)
__device__ float g_y[BB * LL * II];   // predictor outputs (full fp32)
__device__ float g_rWsum[1024 * 256]; // rWih + rWhh
__device__ float g_rb[1024];
__device__ float g_pb[128];
__device__ unsigned g_count = 0;
__device__ unsigned g_gen = 0;

// ---------------- helpers ------------------------------------------------------
__device__ __forceinline__ uint32_t smem_u32(const void* p) {
    uint32_t a;
    asm("{ .reg .u64 t; cvta.to.shared.u64 t, %1; cvt.u32.u64 %0, t; }" : "=r"(a) : "l"(p));
    return a;
}
__device__ __forceinline__ float to_tf32(float x) {
    float r;
    asm("cvt.rna.tf32.f32 %0, %1;" : "=f"(r) : "f"(x));
    return r;
}
__device__ __forceinline__ float sigm(float x) { return 1.f / (1.f + expf(-x)); }
__device__ __forceinline__ uint32_t f2u(float x) { return __float_as_uint(x); }

// m16n8k8 tf32 mma: D += A(16x8 row) * B(8x8 col)
__device__ __forceinline__ void mma8(float* c, const uint32_t* a, uint32_t b0, uint32_t b1) {
    asm volatile("mma.sync.aligned.m16n8k8.row.col.f32.tf32.tf32.f32 "
                 "{%0,%1,%2,%3}, {%4,%5,%6,%7}, {%8,%9}, {%0,%1,%2,%3};"
                 : "+f"(c[0]), "+f"(c[1]), "+f"(c[2]), "+f"(c[3])
                 : "r"(a[0]), "r"(a[1]), "r"(a[2]), "r"(a[3]), "r"(b0), "r"(b1));
}

// cp.async 16B, L2-only (.cg) — cross-SM coherent staging
__device__ __forceinline__ void cp16(uint32_t d, const void* s) {
    asm volatile("cp.async.cg.shared.global [%0], [%1], 16;" :: "r"(d), "l"(s));
}
#define CP_COMMIT() asm volatile("cp.async.commit_group;" ::: "memory")
#define CP_WAIT(n)  asm volatile("cp.async.wait_group %0;" :: "n"(n) : "memory")

// One K=128 half of a 128x64 CTA tile: warp grid 4(M=32) x 2(N=32).
// A stride 132 floats, B stride `bstride` floats (both ≡4 mod 32 → conflict-free frags).
__device__ __forceinline__ void mma_half(float (*C)[4], const float* Ab, const float* Bb,
                                         int bstride, int kofs, int gid, int tig,
                                         int wm, int wn) {
#pragma unroll
    for (int ks = 0; ks < 16; ++ks) {
        const int k0 = ks * 8;
        uint32_t a[2][4];
#pragma unroll
        for (int mt = 0; mt < 2; ++mt) {
            const float* ap = Ab + (wm * 32 + mt * 16) * 132 + k0;
            a[mt][0] = f2u(ap[gid * 132 + tig]);
            a[mt][1] = f2u(ap[(gid + 8) * 132 + tig]);
            a[mt][2] = f2u(ap[gid * 132 + tig + 4]);
            a[mt][3] = f2u(ap[(gid + 8) * 132 + tig + 4]);
        }
#pragma unroll
        for (int nt = 0; nt < 4; ++nt) {
            const float* bp = Bb + (wn * 32 + nt * 8 + gid) * bstride + kofs + k0;
            uint32_t b0 = f2u(bp[tig]);
            uint32_t b1 = f2u(bp[tig + 4]);
            mma8(C[nt], a[0], b0, b1);
            mma8(C[4 + nt], a[1], b0, b1);
        }
    }
}

// grid-wide software barrier
__device__ __forceinline__ void grid_sync() {
    __syncthreads();
    if (threadIdx.x == 0) {
        volatile unsigned* genp = &g_gen;
        unsigned gen = *genp;
        __threadfence();
        unsigned prev = atomicAdd(&g_count, 1u);
        if (prev == NBLK - 1) {
            g_count = 0;
            __threadfence();
            *genp = gen + 1;
        } else {
            while (*genp == gen) { __nanosleep(64); }
            __threadfence();
        }
    }
    __syncthreads();
}

// ---------------- decode SMEM layout (byte offsets in dynamic smem) ------------
#define DOFF_A0   0                         // A half buf 0: 128x132 f (67584B)
#define DOFF_A1   67584                     // A half buf 1: 128x132 f
#define DOFF_B    135168                    // B: 64x260 f (66560B)
#define DOFF_BD   201728                    // decode bias 64 f
#define DOFF_BP   201984                    // predictor bias 32 f
#define DEC_SMEM  202112
// overlays (valid when A bufs not in use):
#define DOFF_G    DOFF_A0                   // gates exchange: [64][132] f
#define DOFF_XS   DOFF_A1                   // predictor X: [32][292] f (37376B)
#define DOFF_P    (DOFF_A1 + 37376)         // predictor gate exchange: [4][32][8] f

// stage 128 rows x 128 K-floats of A (row stride 256) into smem stride 132, via cp.async
__device__ __forceinline__ void stage_A(uint32_t Abase, const float* src, int kc0, int tid) {
    int r = tid >> 1;
    int cb = (tid & 1) * 64;
    const float* s = src + r * 256 + kc0 + cb;
    uint32_t d = Abase + (uint32_t)(r * 132 + cb) * 4u;
#pragma unroll
    for (int j = 0; j < 16; ++j) cp16(d + j * 16u, s + j * 4);
}

// stage B: 64 gate rows (n = g*16+hc -> weight row g*256 + ht*16 + hc), K=256,
// rounded to tf32, smem stride 260
__device__ __forceinline__ void stage_B(float* Bb, const float* __restrict__ W, int ht, int tid) {
#pragma unroll
    for (int i = 0; i < 16; ++i) {
        int e = tid + i * NTHR;
        int n = e >> 6, c4 = e & 63;
        int grow = (n >> 4) * 256 + ht * 16 + (n & 15);
        float4 v = *reinterpret_cast<const float4*>(W + grow * 256 + c4 * 4);
        v.x = to_tf32(v.x); v.y = to_tf32(v.y); v.z = to_tf32(v.z); v.w = to_tf32(v.w);
        *reinterpret_cast<float4*>(Bb + n * 260 + c4 * 4) = v;
    }
}

// ---------------- persistent decode + predictor kernel -------------------------
__global__ void __launch_bounds__(NTHR, 1)
decode_kernel(const float* __restrict__ rWih, const float* __restrict__ rWhh,
              const float* __restrict__ pWih, const float* __restrict__ pWhh) {
    extern __shared__ char sm[];
    const uint32_t sbase = smem_u32(sm);
    float* A0 = (float*)(sm + DOFF_A0);
    float* A1 = (float*)(sm + DOFF_A1);
    float* Bb = (float*)(sm + DOFF_B);
    float* biasD = (float*)(sm + DOFF_BD);
    float* biasP = (float*)(sm + DOFF_BP);
    float* G  = (float*)(sm + DOFF_G);
    float* Xs = (float*)(sm + DOFF_XS);
    float* P  = (float*)(sm + DOFF_P);

    const int bid = blockIdx.x;
    const int tid = threadIdx.x;
    const int wid = tid >> 5, lane = tid & 31;
    const int gid = lane >> 2, tig = lane & 3;
    const int wm = wid >> 1, wn = wid & 1;
    // decode: 8 M-tiles(128 rows) x 16 N-tiles(64 gate cols: 4 gates x 16 hcols)
    const int mt = bid >> 4, ht = bid & 15;
    // predictor: 32 M-tiles(32 rows) x 4 col groups(8 icols)
    const int pm = bid >> 2, pic = bid & 3;
    const int pmt = wid >> 2, pnt = wid & 3;  // warp: mtile(16 rows), gate

    // ---- one-time: biases, predictor weight fragments (registers), B(rWih) ----
    if (tid < 64) biasD[tid] = g_rb[(tid >> 4) * 256 + ht * 16 + (tid & 15)];
    if (tid < 32) biasP[tid] = g_pb[(tid >> 3) * 32 + pic * 8 + (tid & 7)];

    float pB[36][2];  // predictor B frags, resident 128 steps
    {
        const int prow = pnt * 32 + pic * 8 + gid;
#pragma unroll
        for (int ks = 0; ks < 36; ++ks) {
            int k0 = ks * 8 + tig;
            float v0 = (k0 < 256) ? pWih[prow * 256 + k0] : pWhh[prow * 32 + (k0 - 256)];
            int k1 = k0 + 4;
            float v1 = (k1 < 256) ? pWih[prow * 256 + k1] : pWhh[prow * 32 + (k1 - 256)];
            pB[ks][0] = to_tf32(v0);
            pB[ks][1] = to_tf32(v1);
        }
    }

    // decode cell state: thread owns row r2 = tid>>1 (CTA-local), hcols (tid&1)*8..+8
    const int r2 = tid >> 1, hcb = (tid & 1) * 8;
    float creg[8];
    {
        const float* cp = &g_c[(mt * 128 + r2) * 256 + ht * 16 + hcb];
        float4 c0 = *reinterpret_cast<const float4*>(cp);
        float4 c1 = *reinterpret_cast<const float4*>(cp + 4);
        creg[0] = c0.x; creg[1] = c0.y; creg[2] = c0.z; creg[3] = c0.w;
        creg[4] = c1.x; creg[5] = c1.y; creg[6] = c1.z; creg[7] = c1.w;
    }
    float cp_reg = 0.f;  // predictor cell (thread owns (pm*32 + tid>>3, pic*8 + tid&7))

    stage_B(Bb, rWih, ht, tid);   // step-0 first B
    __syncthreads();

    for (int t = 0; t < LL; ++t) {
        const int ib = t & 1, ob = ib ^ 1;

        float C[8][4];
#pragma unroll
        for (int i = 0; i < 8; ++i)
#pragma unroll
            for (int j = 0; j < 4; ++j) C[i][j] = 0.f;

        // one A source, both K halves, double-buffered via cp.async
        auto do_pair = [&](const float* src) {
            stage_A(sbase + DOFF_A0, src, 0, tid);   CP_COMMIT();
            stage_A(sbase + DOFF_A1, src, 128, tid); CP_COMMIT();
            CP_WAIT(1); __syncthreads();
            mma_half(C, A0, Bb, 260, 0, gid, tig, wm, wn);
            CP_WAIT(0); __syncthreads();
            mma_half(C, A1, Bb, 260, 128, gid, tig, wm, wn);
            __syncthreads();
        };

        if (t == 0) {
            do_pair(g_x0 + mt * 128 * 256);          // x0 @ rWih^T
            stage_B(Bb, rWhh, ht, tid); __syncthreads();
            do_pair(g_h[0] + mt * 128 * 256);        // + h0 @ rWhh^T
        } else {
            do_pair(g_h[ib] + mt * 128 * 256);       // h @ (rWih+rWhh)^T
        }

        // ---- gate exchange: C frags -> G[c][r] (overlay A0; A bufs now free) ----
#pragma unroll
        for (int m2 = 0; m2 < 2; ++m2)
#pragma unroll
            for (int nt = 0; nt < 4; ++nt) {
                int r = wm * 32 + m2 * 16 + gid;
                int c = wn * 32 + nt * 8 + tig * 2;
                float* g0 = G + c * 132 + r;
                g0[0]       = C[m2 * 4 + nt][0];
                g0[132]     = C[m2 * 4 + nt][1];
                g0[8]       = C[m2 * 4 + nt][2];
                g0[132 + 8] = C[m2 * 4 + nt][3];
            }
        if (t == 0) stage_B(Bb, g_rWsum, ht, tid);   // steady-state B for steps 1+
        __syncthreads();

        // ---- pointwise LSTM update (thread-owned cells) ----
        {
            float hv[8];
#pragma unroll
            for (int j = 0; j < 8; ++j) {
                int hc = hcb + j;
                float iv = G[hc * 132 + r2]        + biasD[hc];
                float fv = G[(16 + hc) * 132 + r2] + biasD[16 + hc];
                float gv = G[(32 + hc) * 132 + r2] + biasD[32 + hc];
                float ov = G[(48 + hc) * 132 + r2] + biasD[48 + hc];
                float cn = sigm(fv) * creg[j] + sigm(iv) * tanhf(gv);
                creg[j] = cn;
                hv[j] = to_tf32(sigm(ov) * tanhf(cn));  // pre-round for tf32 mma
            }
            float* dst = &g_h[ob][(mt * 128 + r2) * 256 + ht * 16 + hcb];
            *reinterpret_cast<float4*>(dst)     = make_float4(hv[0], hv[1], hv[2], hv[3]);
            *reinterpret_cast<float4*>(dst + 4) = make_float4(hv[4], hv[5], hv[6], hv[7]);
        }

        grid_sync();  // publishes h[ob] chip-wide (one barrier per step)

        // ================= predictor LSTM step t (tensor path) =================
        // stage X = [h[ob] rows pm*32..+32 (256) | hp[ib] (32)] into Xs[32][292]
        {
            int r = tid >> 3, cb = (tid & 7) * 36;
            const float* hrow = g_h[ob] + (pm * 32 + r) * 256;
            const float* prow = g_hp[ib] + (pm * 32 + r) * 32;
#pragma unroll
            for (int j = 0; j < 9; ++j) {
                int col = cb + j * 4;
                float4 v;
                if (col < 256) v = __ldcg(reinterpret_cast<const float4*>(hrow + col));
                else           v = __ldcg(reinterpret_cast<const float4*>(prow + (col - 256)));
                *reinterpret_cast<float4*>(Xs + r * 292 + col) = v;
            }
        }
        __syncthreads();

        float pc[4] = {0.f, 0.f, 0.f, 0.f};
#pragma unroll
        for (int ks = 0; ks < 36; ++ks) {
            const float* xp = Xs + pmt * 16 * 292 + ks * 8;
            uint32_t a[4];
            a[0] = f2u(xp[gid * 292 + tig]);
            a[1] = f2u(xp[(gid + 8) * 292 + tig]);
            a[2] = f2u(xp[gid * 292 + tig + 4]);
            a[3] = f2u(xp[(gid + 8) * 292 + tig + 4]);
            mma8(pc, a, f2u(pB[ks][0]), f2u(pB[ks][1]));
        }
        // exchange via P[g][ml][ic]
        {
            int ml = pmt * 16 + gid;
            float* p0 = P + (pnt * 32 + ml) * 8 + tig * 2;
            p0[0] = pc[0]; p0[1] = pc[1];
            p0[64] = pc[2]; p0[65] = pc[3];   // ml+8 => +8*8
        }
        __syncthreads();
        {
            int ml = tid >> 3, ic = tid & 7;
            float iv = P[(0 * 32 + ml) * 8 + ic] + biasP[ic];
            float fv = P[(1 * 32 + ml) * 8 + ic] + biasP[8 + ic];
            float gv = P[(2 * 32 + ml) * 8 + ic] + biasP[16 + ic];
            float ov = P[(3 * 32 + ml) * 8 + ic] + biasP[24 + ic];
            float cn = sigm(fv) * cp_reg + sigm(iv) * tanhf(gv);
            cp_reg = cn;
            float hn = sigm(ov) * tanhf(cn);
            int m = pm * 32 + ml, icol = pic * 8 + ic;
            g_hp[ob][m * 32 + icol] = to_tf32(hn);
            g_y[(m * LL + t) * II + icol] = hn;
        }
        __syncthreads();  // protect Xs/P (A1 overlay) before next step's cp.async
    }
}

// ---------------- tf32 tensor GEMM for the MLP front ---------------------------
__device__ __forceinline__ float* buf_ptr(int id) {
    switch (id) {
        case 0: return g_t0;
        case 1: return g_t1;
        case 2: return g_h[0];
        case 3: return g_c;
        case 4: return g_x0;
    }
    return nullptr;
}

#define GOFF_A 0                       // [128][132] f
#define GOFF_B 67584                   // [64][132] f
#define GEMM_SMEM (67584 + 33792)

__global__ void __launch_bounds__(256, 1)
gemm_tf32(const float* __restrict__ Aext, int a_id,
          const float* __restrict__ W, const float* __restrict__ bias,
          int c_id, int M, int N, int K, int act) {
    extern __shared__ char sm[];
    float* Ab = (float*)(sm + GOFF_A);
    float* Bb = (float*)(sm + GOFF_B);
    const float* A = Aext ? Aext : buf_ptr(a_id);
    float* Cb = buf_ptr(c_id);

    const int tid = threadIdx.x;
    const int lane = tid & 31, wid = tid >> 5;
    const int gid = lane >> 2, tig = lane & 3;
    const int wm = wid >> 1, wn = wid & 1;
    const int m0 = blockIdx.y * 128, n0 = blockIdx.x * 64;

    float C[8][4];
#pragma unroll
    for (int i = 0; i < 8; ++i)
#pragma unroll
        for (int j = 0; j < 4; ++j) C[i][j] = 0.f;

    for (int kk = 0; kk < K; kk += 128) {
        // stage A 128x128 (rounded)
        {
            int r = tid >> 1, cb = (tid & 1) * 64;
            const float* s = A + (m0 + r) * K + kk + cb;
#pragma unroll
            for (int j = 0; j < 16; ++j) {
                float4 v = *reinterpret_cast<const float4*>(s + j * 4);
                v.x = to_tf32(v.x); v.y = to_tf32(v.y); v.z = to_tf32(v.z); v.w = to_tf32(v.w);
                *reinterpret_cast<float4*>(Ab + r * 132 + cb + j * 4) = v;
            }
        }
        // stage B 64x128 (rounded)
#pragma unroll
        for (int i = 0; i < 8; ++i) {
            int e = tid + i * 256;
            int n = e >> 5, c4 = e & 31;
            float4 v = *reinterpret_cast<const float4*>(W + (n0 + n) * K + kk + c4 * 4);
            v.x = to_tf32(v.x); v.y = to_tf32(v.y); v.z = to_tf32(v.z); v.w = to_tf32(v.w);
            *reinterpret_cast<float4*>(Bb + n * 132 + c4 * 4) = v;
        }
        __syncthreads();
        mma_half(C, Ab, Bb, 132, 0, gid, tig, wm, wn);
        __syncthreads();
    }

#pragma unroll
    for (int m2 = 0; m2 < 2; ++m2)
#pragma unroll
        for (int nt = 0; nt < 4; ++nt) {
            int r = m0 + wm * 32 + m2 * 16 + gid;
            int c = n0 + wn * 32 + nt * 8 + tig * 2;
            float b0 = bias[c], b1 = bias[c + 1];
            float v0 = C[m2 * 4 + nt][0] + b0, v1 = C[m2 * 4 + nt][1] + b1;
            float v2 = C[m2 * 4 + nt][2] + b0, v3 = C[m2 * 4 + nt][3] + b1;
            if (act) {
                v0 = v0 >= 0.f ? v0 : 0.2f * v0;
                v1 = v1 >= 0.f ? v1 : 0.2f * v1;
                v2 = v2 >= 0.f ? v2 : 0.2f * v2;
                v3 = v3 >= 0.f ? v3 : 0.2f * v3;
            }
            *reinterpret_cast<float2*>(Cb + r * N + c) =
                make_float2(to_tf32(v0), to_tf32(v1));
            *reinterpret_cast<float2*>(Cb + (r + 8) * N + c) =
                make_float2(to_tf32(v2), to_tf32(v3));
        }
}

// ---------------- init ---------------------------------------------------------
__global__ void init_kernel(const float* __restrict__ rWih, const float* __restrict__ rWhh,
                            const float* __restrict__ rbih, const float* __restrict__ rbhh,
                            const float* __restrict__ pbih, const float* __restrict__ pbhh) {
    int i = blockIdx.x * blockDim.x + threadIdx.x;
    if (i < 1024 * 256) g_rWsum[i] = rWih[i] + rWhh[i];
    if (i < 1024) g_rb[i] = rbih[i] + rbhh[i];
    if (i < 128) g_pb[i] = pbih[i] + pbhh[i];
    if (i < BB * II) { g_hp[0][i] = 0.f; g_hp[1][i] = 0.f; }
}

// ---------------- epilogue: softmax over 31 channels + sigmoid on last ---------
__global__ void __launch_bounds__(256)
out_kernel(float* __restrict__ out) {
    int gw = (blockIdx.x * blockDim.x + threadIdx.x) >> 5;
    int lane = threadIdx.x & 31;
    if (gw >= BB * LL) return;
    float v = g_y[gw * 32 + lane];
    float sv = (lane < 31) ? v : -3.0e38f;
    float mx = sv;
#pragma unroll
    for (int o = 16; o; o >>= 1) mx = fmaxf(mx, __shfl_xor_sync(0xffffffffu, mx, o));
    float e = (lane < 31) ? expf(sv - mx) : 0.f;
    float s = e;
#pragma unroll
    for (int o = 16; o; o >>= 1) s += __shfl_xor_sync(0xffffffffu, s, o);
    float r = (lane < 31) ? (e / s) : (1.f / (1.f + expf(-v)));
    out[gw * 32 + lane] = r;
}

// ---------------- launcher ----------------------------------------------------
extern "C" void kernel_launch(void* const* d_in, const int* in_sizes, int n_in,
                              void* d_out, int out_size) {
    const float* x    = (const float*)d_in[0];
    const float* W1   = (const float*)d_in[1];  const float* b1  = (const float*)d_in[2];
    const float* W2   = (const float*)d_in[3];  const float* b2  = (const float*)d_in[4];
    const float* W3   = (const float*)d_in[5];  const float* b3  = (const float*)d_in[6];
    const float* Wh1  = (const float*)d_in[7];  const float* bh1 = (const float*)d_in[8];
    const float* Wh2  = (const float*)d_in[9];  const float* bh2 = (const float*)d_in[10];
    const float* Wc1  = (const float*)d_in[11]; const float* bc1 = (const float*)d_in[12];
    const float* Wc2  = (const float*)d_in[13]; const float* bc2 = (const float*)d_in[14];
    const float* Wx1  = (const float*)d_in[15]; const float* bx1 = (const float*)d_in[16];
    const float* Wx2  = (const float*)d_in[17]; const float* bx2 = (const float*)d_in[18];
    const float* rWih = (const float*)d_in[19]; const float* rWhh = (const float*)d_in[20];
    const float* rbih = (const float*)d_in[21]; const float* rbhh = (const float*)d_in[22];
    const float* pWih = (const float*)d_in[23]; const float* pWhh = (const float*)d_in[24];
    const float* pbih = (const float*)d_in[25]; const float* pbhh = (const float*)d_in[26];
    float* out = (float*)d_out;

    cudaFuncSetAttribute(decode_kernel, cudaFuncAttributeMaxDynamicSharedMemorySize, DEC_SMEM);
    cudaFuncSetAttribute(gemm_tf32, cudaFuncAttributeMaxDynamicSharedMemorySize, GEMM_SMEM);

    init_kernel<<<1024, 256>>>(rWih, rWhh, rbih, rbhh, pbih, pbhh);

    dim3 blk(256);
    // buf ids: 0=g_t0, 1=g_t1, 2=g_h[0], 3=g_c, 4=g_x0
    gemm_tf32<<<dim3(8, 8), blk, GEMM_SMEM>>>(x,    -1, W1,  b1,  1, BB, 512, 128, 1);
    gemm_tf32<<<dim3(8, 8), blk, GEMM_SMEM>>>(NULL,  1, W2,  b2,  0, BB, 512, 512, 1);
    gemm_tf32<<<dim3(8, 8), blk, GEMM_SMEM>>>(NULL,  0, W3,  b3,  1, BB, 512, 512, 1);
    gemm_tf32<<<dim3(8, 8), blk, GEMM_SMEM>>>(NULL,  1, Wh1, bh1, 0, BB, 512, 512, 1);
    gemm_tf32<<<dim3(4, 8), blk, GEMM_SMEM>>>(NULL,  0, Wh2, bh2, 2, BB, 256, 512, 0); // h0
    gemm_tf32<<<dim3(8, 8), blk, GEMM_SMEM>>>(NULL,  1, Wc1, bc1, 0, BB, 512, 512, 1);
    gemm_tf32<<<dim3(4, 8), blk, GEMM_SMEM>>>(NULL,  0, Wc2, bc2, 3, BB, 256, 512, 0); // c0
    gemm_tf32<<<dim3(8, 8), blk, GEMM_SMEM>>>(NULL,  1, Wx1, bx1, 0, BB, 512, 512, 1);
    gemm_tf32<<<dim3(4, 8), blk, GEMM_SMEM>>>(NULL,  0, Wx2, bx2, 4, BB, 256, 512, 0); // x0

    decode_kernel<<<NBLK, NTHR, DEC_SMEM>>>(rWih, rWhh, pWih, pWhh);

    out_kernel<<<(BB * LL) / 8, 256>>>(out);
}

// round 8
// speedup vs baseline: 4.4778x; 2.0026x over previous
#include <cuda_runtime.h>
#include <cuda_fp16.h>
#include <math.h>
#include <stdint.h>

// Problem dims
#define BB 1024
#define HH 256
#define II 32
#define LL 128

#define NBLK 128
#define NTHR 512

// ---------------- device scratch ----------------------------------------------
__device__ __align__(16) __half g_Wsum_h[1024 * 256];  // fp16(rWih + rWhh)
__device__ __align__(16) __half g_Wih_h[1024 * 256];
__device__ __align__(16) __half g_Whh_h[1024 * 256];
__device__ __align__(16) __half g_hb[2][BB * HH];      // decode hidden ping-pong (fp16)
__device__ __align__(16) float  g_c[BB * HH];          // decode cell init (fp32)
__device__ __align__(16) __half g_x0h[BB * HH];
__device__ __align__(16) __half g_hp[2][BB * II];      // predictor hidden ping-pong
__device__ __align__(16) float  g_y[BB * LL * II];     // predictor outputs (fp32)
__device__ float g_rb[1024];
__device__ float g_pb[128];
__device__ unsigned g_count = 0;
__device__ unsigned g_gen = 0;
// fp16 activations + weights for the MLP front
__device__ __align__(16) __half g_xh[BB * 128];
__device__ __align__(16) __half g_t0h[BB * 512];
__device__ __align__(16) __half g_t1h[BB * 512];
__device__ __align__(16) __half g_W1h[512 * 128];
__device__ __align__(16) __half g_W2h[512 * 512];
__device__ __align__(16) __half g_W3h[512 * 512];
__device__ __align__(16) __half g_Wh1h[512 * 512];
__device__ __align__(16) __half g_Wc1h[512 * 512];
__device__ __align__(16) __half g_Wx1h[512 * 512];
__device__ __align__(16) __half g_Wh2h[256 * 512];
__device__ __align__(16) __half g_Wc2h[256 * 512];
__device__ __align__(16) __half g_Wx2h[256 * 512];

// ---------------- helpers ------------------------------------------------------
__device__ __forceinline__ uint32_t smem_u32(const void* p) {
    uint32_t a;
    asm("{ .reg .u64 t; cvta.to.shared.u64 t, %1; cvt.u32.u64 %0, t; }" : "=r"(a) : "l"(p));
    return a;
}
__device__ __forceinline__ float sigm(float x) { return 1.f / (1.f + expf(-x)); }

// m16n8k16 fp16 mma, fp32 accum
__device__ __forceinline__ void mma16(float* c, const uint32_t* a, uint32_t b0, uint32_t b1) {
    asm volatile("mma.sync.aligned.m16n8k16.row.col.f32.f16.f16.f32 "
                 "{%0,%1,%2,%3}, {%4,%5,%6,%7}, {%8,%9}, {%0,%1,%2,%3};"
                 : "+f"(c[0]), "+f"(c[1]), "+f"(c[2]), "+f"(c[3])
                 : "r"(a[0]), "r"(a[1]), "r"(a[2]), "r"(a[3]), "r"(b0), "r"(b1));
}
__device__ __forceinline__ void cp16(uint32_t d, const void* s) {
    asm volatile("cp.async.cg.shared.global [%0], [%1], 16;" :: "r"(d), "l"(s));
}
#define CP_COMMIT() asm volatile("cp.async.commit_group;" ::: "memory")
#define CP_WAIT(n)  asm volatile("cp.async.wait_group %0;" :: "n"(n) : "memory")

__device__ __forceinline__ uint32_t lds32(const __half* p) { return *reinterpret_cast<const uint32_t*>(p); }

// grid-wide software barrier
__device__ __forceinline__ void grid_sync() {
    __syncthreads();
    if (threadIdx.x == 0) {
        volatile unsigned* genp = &g_gen;
        unsigned gen = *genp;
        __threadfence();
        unsigned prev = atomicAdd(&g_count, 1u);
        if (prev == NBLK - 1) {
            g_count = 0;
            __threadfence();
            *genp = gen + 1;
        } else {
            while (*genp == gen) { __nanosleep(64); }
            __threadfence();
        }
    }
    __syncthreads();
}

// ---------------- decode SMEM layout (byte offsets) ----------------------------
// B: [128][264]h resident weights; A0/A1: [64][136]h K-halves; overlays on A region.
#define DOFF_B    0
#define DOFF_A0   67584
#define DOFF_A1   84992
#define DOFF_BD   102400        // 128 f
#define DOFF_BP   102912        // 32 f
#define DEC_SMEM  103040
#define DOFF_G    DOFF_A0       // gates exchange [64][132] f (33792B <= 34816)
#define DOFF_XS   DOFF_A0       // predictor X [32][296]h (18944B)
#define DOFF_P    (DOFF_A0 + 18944)  // predictor exchange [4][32][8] f (4096B)

// stage B: 128 gate rows x 256 halves into stride-264 smem (row n = g*32+hcl)
__device__ __forceinline__ void stage_Bh(__half* Bb, const __half* __restrict__ W,
                                         int nt8, int tid) {
#pragma unroll
    for (int i = 0; i < 8; ++i) {
        int e = tid + i * NTHR;
        int n = e >> 5, cb = (e & 31) * 8;
        int grow = (n >> 5) * 256 + nt8 * 32 + (n & 31);
        *reinterpret_cast<uint4*>(Bb + n * 264 + cb) =
            *reinterpret_cast<const uint4*>(W + grow * 256 + cb);
    }
}
// stage A half: 64 rows x 128 halves (src row stride 256) via cp.async
__device__ __forceinline__ void stage_A(uint32_t Abase, const __half* src, int kc0, int tid) {
#pragma unroll
    for (int i = 0; i < 2; ++i) {
        int e = tid + i * NTHR;
        int r = e >> 4, cb = (e & 15) * 8;
        cp16(Abase + (uint32_t)(r * 136 + cb) * 2u, src + r * 256 + kc0 + cb);
    }
}

// one K=128 half: warp tile 32x16 (wm 0/1: rows, wn 0..7: cols), 8 ksteps
__device__ __forceinline__ void mma_half(float (*C)[4], const __half* Ab, const __half* Bb,
                                         int bkofs, int wm, int wn, int gid, int tig) {
#pragma unroll
    for (int ks = 0; ks < 8; ++ks) {
        const int k0 = ks * 16;
        uint32_t a[2][4];
#pragma unroll
        for (int mf = 0; mf < 2; ++mf) {
            const __half* ap = Ab + (wm * 32 + mf * 16) * 136 + k0 + 2 * tig;
            a[mf][0] = lds32(ap + gid * 136);
            a[mf][1] = lds32(ap + (gid + 8) * 136);
            a[mf][2] = lds32(ap + gid * 136 + 8);
            a[mf][3] = lds32(ap + (gid + 8) * 136 + 8);
        }
#pragma unroll
        for (int nf = 0; nf < 2; ++nf) {
            const __half* bp = Bb + (wn * 16 + nf * 8 + gid) * 264 + bkofs + k0 + 2 * tig;
            uint32_t b0 = lds32(bp);
            uint32_t b1 = lds32(bp + 8);
            mma16(C[nf], a[0], b0, b1);
            mma16(C[2 + nf], a[1], b0, b1);
        }
    }
}

// ---------------- persistent decode + predictor kernel -------------------------
__global__ void __launch_bounds__(NTHR, 1)
decode_kernel(const float* __restrict__ pWih, const float* __restrict__ pWhh) {
    extern __shared__ char sm[];
    const uint32_t sbase = smem_u32(sm);
    __half* Bb = (__half*)(sm + DOFF_B);
    __half* A0 = (__half*)(sm + DOFF_A0);
    __half* A1 = (__half*)(sm + DOFF_A1);
    float* biasD = (float*)(sm + DOFF_BD);
    float* biasP = (float*)(sm + DOFF_BP);
    float* G  = (float*)(sm + DOFF_G);
    __half* Xs = (__half*)(sm + DOFF_XS);
    float* P  = (float*)(sm + DOFF_P);

    const int bid = blockIdx.x;
    const int tid = threadIdx.x;
    const int wid = tid >> 5, lane = tid & 31;
    const int gid = lane >> 2, tig = lane & 3;
    const int wm = wid >> 3, wn = wid & 7;       // decode warp grid 2M x 8N
    // decode: 16 M-tiles(64 rows) x 8 col-tiles(32 hcols x 4 gates)
    const int mt = bid >> 3, nt8 = bid & 7;
    // predictor: 32 M-tiles(32 rows) x 4 col groups(8 icols)
    const int pm = bid >> 2, pic = bid & 3;
    const int pmt = (wid >> 2) & 1, png = wid & 3;  // warps 0..7

    // ---- one-time: biases, predictor B fragments (registers), B(rWih) ----
    if (tid < 128) biasD[tid] = g_rb[(tid >> 5) * 256 + nt8 * 32 + (tid & 31)];
    if (tid < 32)  biasP[tid] = g_pb[(tid >> 3) * 32 + pic * 8 + (tid & 7)];

    uint32_t pB[18][2];
    if (wid < 8) {
        const int prow = png * 32 + pic * 8 + gid;
#pragma unroll
        for (int ks = 0; ks < 18; ++ks) {
#pragma unroll
            for (int hh = 0; hh < 2; ++hh) {
                int k = ks * 16 + 2 * tig + hh * 8;
                float v0 = (k < 256) ? pWih[prow * 256 + k] : pWhh[prow * 32 + (k - 256)];
                float v1 = (k + 1 < 256) ? pWih[prow * 256 + k + 1] : pWhh[prow * 32 + (k + 1 - 256)];
                __half2 h2 = __floats2half2_rn(v0, v1);
                pB[ks][hh] = *reinterpret_cast<uint32_t*>(&h2);
            }
        }
    }

    // decode cell state: thread owns row r = tid>>3 (64 rows), hcols (tid&7)*4..+4
    const int rr = tid >> 3, hq = (tid & 7) * 4;
    float creg[4];
    {
        float4 cv = *reinterpret_cast<const float4*>(g_c + (mt * 64 + rr) * 256 + nt8 * 32 + hq);
        creg[0] = cv.x; creg[1] = cv.y; creg[2] = cv.z; creg[3] = cv.w;
    }
    float cp_reg = 0.f;  // predictor cell (tid<256 threads own one cell)

    stage_Bh(Bb, g_Wih_h, nt8, tid);  // step-0 first B
    __syncthreads();

    for (int t = 0; t < LL; ++t) {
        const int ib = t & 1, ob = ib ^ 1;

        float C[4][4];
#pragma unroll
        for (int i = 0; i < 4; ++i)
#pragma unroll
            for (int j = 0; j < 4; ++j) C[i][j] = 0.f;

        auto do_pair = [&](const __half* src) {
            stage_A(sbase + DOFF_A0, src, 0, tid);   CP_COMMIT();
            stage_A(sbase + DOFF_A1, src, 128, tid); CP_COMMIT();
            CP_WAIT(1); __syncthreads();
            mma_half(C, A0, Bb, 0, wm, wn, gid, tig);
            CP_WAIT(0); __syncthreads();
            mma_half(C, A1, Bb, 128, wm, wn, gid, tig);
            __syncthreads();
        };

        if (t == 0) {
            do_pair(g_x0h + mt * 64 * 256);                 // x0 @ rWih^T
            stage_Bh(Bb, g_Whh_h, nt8, tid); __syncthreads();
            do_pair(g_hb[0] + mt * 64 * 256);               // + h0 @ rWhh^T
            stage_Bh(Bb, g_Wsum_h, nt8, tid);               // steady-state B (synced below)
        } else {
            do_pair(g_hb[ib] + mt * 64 * 256);              // h @ (rWih+rWhh)^T
        }

        // ---- gate exchange: C frags -> G[r][c] (overlay A bufs, now dead) ----
#pragma unroll
        for (int mf = 0; mf < 2; ++mf)
#pragma unroll
            for (int nf = 0; nf < 2; ++nf) {
                int r = wm * 32 + mf * 16 + gid;
                int cl = wn * 16 + nf * 8 + 2 * tig;
                *reinterpret_cast<float2*>(&G[r * 132 + cl]) =
                    make_float2(C[mf * 2 + nf][0], C[mf * 2 + nf][1]);
                *reinterpret_cast<float2*>(&G[(r + 8) * 132 + cl]) =
                    make_float2(C[mf * 2 + nf][2], C[mf * 2 + nf][3]);
            }
        __syncthreads();

        // ---- pointwise LSTM update (thread-owned 4 cells) ----
        {
            __half hv[4];
#pragma unroll
            for (int j = 0; j < 4; ++j) {
                int hcl = hq + j;
                float iv = G[rr * 132 + hcl]      + biasD[hcl];
                float fv = G[rr * 132 + 32 + hcl] + biasD[32 + hcl];
                float gv = G[rr * 132 + 64 + hcl] + biasD[64 + hcl];
                float ov = G[rr * 132 + 96 + hcl] + biasD[96 + hcl];
                float cn = sigm(fv) * creg[j] + sigm(iv) * tanhf(gv);
                creg[j] = cn;
                hv[j] = __float2half(sigm(ov) * tanhf(cn));
            }
            __half* dst = g_hb[ob] + (mt * 64 + rr) * 256 + nt8 * 32 + hq;
            *reinterpret_cast<__half2*>(dst)     = __halves2half2(hv[0], hv[1]);
            *reinterpret_cast<__half2*>(dst + 2) = __halves2half2(hv[2], hv[3]);
        }

        grid_sync();  // publishes h[ob] chip-wide

        // ================= predictor LSTM step t =================
        // stage X = [h rows pm*32..+32 (256) | hp (32)] into Xs[32][296]
        {
#pragma unroll
            for (int i = 0; i < 2; ++i) {
                int e = tid + i * NTHR;
                int r = e >> 5, cb = (e & 31) * 8;
                uint4 v = __ldcg(reinterpret_cast<const uint4*>(
                    g_hb[ob] + (pm * 32 + r) * 256 + cb));
                *reinterpret_cast<uint4*>(Xs + r * 296 + cb) = v;
            }
            if (tid < 128) {
                int r = tid >> 2, cb = (tid & 3) * 8;
                uint4 v = __ldcg(reinterpret_cast<const uint4*>(
                    g_hp[ib] + (pm * 32 + r) * 32 + cb));
                *reinterpret_cast<uint4*>(Xs + r * 296 + 256 + cb) = v;
            }
        }
        __syncthreads();

        if (wid < 8) {
            float pc[4] = {0.f, 0.f, 0.f, 0.f};
#pragma unroll
            for (int ks = 0; ks < 18; ++ks) {
                const __half* xp = Xs + (pmt * 16) * 296 + ks * 16 + 2 * tig;
                uint32_t a[4];
                a[0] = lds32(xp + gid * 296);
                a[1] = lds32(xp + (gid + 8) * 296);
                a[2] = lds32(xp + gid * 296 + 8);
                a[3] = lds32(xp + (gid + 8) * 296 + 8);
                mma16(pc, a, pB[ks][0], pB[ks][1]);
            }
            int ml = pmt * 16 + gid;
            *reinterpret_cast<float2*>(&P[(png * 32 + ml) * 8 + 2 * tig]) =
                make_float2(pc[0], pc[1]);
            *reinterpret_cast<float2*>(&P[(png * 32 + ml + 8) * 8 + 2 * tig]) =
                make_float2(pc[2], pc[3]);
        }
        __syncthreads();
        if (tid < 256) {
            int ml = tid >> 3, ic = tid & 7;
            float iv = P[(0  + ml) * 8 + ic] + biasP[ic];
            float fv = P[(32 + ml) * 8 + ic] + biasP[8 + ic];
            float gv = P[(64 + ml) * 8 + ic] + biasP[16 + ic];
            float ov = P[(96 + ml) * 8 + ic] + biasP[24 + ic];
            float cn = sigm(fv) * cp_reg + sigm(iv) * tanhf(gv);
            cp_reg = cn;
            float hn = sigm(ov) * tanhf(cn);
            int m = pm * 32 + ml, icol = pic * 8 + ic;
            g_hp[ob][m * 32 + icol] = __float2half(hn);
            g_y[(m * LL + t) * II + icol] = hn;
        }
        __syncthreads();  // protect Xs/P overlays before next step's cp.async
    }
}

// ---------------- fp16 tensor GEMM for the MLP front: C = act(A @ W^T + b) -----
__global__ void __launch_bounds__(256, 2)
gemm_h(const __half* __restrict__ A, const __half* __restrict__ W,
       const float* __restrict__ bias, __half* __restrict__ Ch, float* __restrict__ Cf,
       int N, int K, int act) {
    __shared__ __half As[64 * 72];
    __shared__ __half Bs[64 * 72];
    const int tid = threadIdx.x;
    const int wid = tid >> 5, lane = tid & 31;
    const int gid = lane >> 2, tig = lane & 3;
    const int wm = wid >> 2, wn = wid & 3;       // 2M x 4N warp grid, warp 32x16
    const int m0 = blockIdx.y * 64, n0 = blockIdx.x * 64;

    float C[4][4];
#pragma unroll
    for (int i = 0; i < 4; ++i)
#pragma unroll
        for (int j = 0; j < 4; ++j) C[i][j] = 0.f;

    for (int kk = 0; kk < K; kk += 64) {
        // FIXED staging: full 64 rows x 64 cols per tile (2x uint4 per thread each)
        {
            int r = tid >> 2, cb = (tid & 3) * 16;
            *reinterpret_cast<uint4*>(As + r * 72 + cb) =
                *reinterpret_cast<const uint4*>(A + (m0 + r) * K + kk + cb);
            *reinterpret_cast<uint4*>(As + r * 72 + cb + 8) =
                *reinterpret_cast<const uint4*>(A + (m0 + r) * K + kk + cb + 8);
            *reinterpret_cast<uint4*>(Bs + r * 72 + cb) =
                *reinterpret_cast<const uint4*>(W + (n0 + r) * K + kk + cb);
            *reinterpret_cast<uint4*>(Bs + r * 72 + cb + 8) =
                *reinterpret_cast<const uint4*>(W + (n0 + r) * K + kk + cb + 8);
        }
        __syncthreads();
#pragma unroll
        for (int ks = 0; ks < 4; ++ks) {
            const int k0 = ks * 16;
            uint32_t a[2][4];
#pragma unroll
            for (int mf = 0; mf < 2; ++mf) {
                const __half* ap = As + (wm * 32 + mf * 16) * 72 + k0 + 2 * tig;
                a[mf][0] = lds32(ap + gid * 72);
                a[mf][1] = lds32(ap + (gid + 8) * 72);
                a[mf][2] = lds32(ap + gid * 72 + 8);
                a[mf][3] = lds32(ap + (gid + 8) * 72 + 8);
            }
#pragma unroll
            for (int nf = 0; nf < 2; ++nf) {
                const __half* bp = Bs + (wn * 16 + nf * 8 + gid) * 72 + k0 + 2 * tig;
                uint32_t b0 = lds32(bp);
                uint32_t b1 = lds32(bp + 8);
                mma16(C[nf], a[0], b0, b1);
                mma16(C[2 + nf], a[1], b0, b1);
            }
        }
        __syncthreads();
    }

#pragma unroll
    for (int mf = 0; mf < 2; ++mf)
#pragma unroll
        for (int nf = 0; nf < 2; ++nf) {
            int r = m0 + wm * 32 + mf * 16 + gid;
            int c = n0 + wn * 16 + nf * 8 + 2 * tig;
            float b0 = bias[c], b1 = bias[c + 1];
            float v0 = C[mf * 2 + nf][0] + b0, v1 = C[mf * 2 + nf][1] + b1;
            float v2 = C[mf * 2 + nf][2] + b0, v3 = C[mf * 2 + nf][3] + b1;
            if (act) {
                v0 = v0 >= 0.f ? v0 : 0.2f * v0;
                v1 = v1 >= 0.f ? v1 : 0.2f * v1;
                v2 = v2 >= 0.f ? v2 : 0.2f * v2;
                v3 = v3 >= 0.f ? v3 : 0.2f * v3;
            }
            if (Ch) {
                *reinterpret_cast<__half2*>(Ch + r * N + c)       = __floats2half2_rn(v0, v1);
                *reinterpret_cast<__half2*>(Ch + (r + 8) * N + c) = __floats2half2_rn(v2, v3);
            } else {
                *reinterpret_cast<float2*>(Cf + r * N + c)       = make_float2(v0, v1);
                *reinterpret_cast<float2*>(Cf + (r + 8) * N + c) = make_float2(v2, v3);
            }
        }
}

// ---------------- init: convert weights/activations to fp16, sums, zeros -------
__global__ void init_kernel(const float* x, const float* W1, const float* W2, const float* W3,
                            const float* Wh1, const float* Wc1, const float* Wx1,
                            const float* Wh2, const float* Wc2, const float* Wx2,
                            const float* rWih, const float* rWhh,
                            const float* rbih, const float* rbhh,
                            const float* pbih, const float* pbhh) {
    const int i0 = blockIdx.x * blockDim.x + threadIdx.x;
    const int ns = gridDim.x * blockDim.x;
    for (int j = i0; j < 1024 * 256; j += ns) {
        float a = rWih[j], b = rWhh[j];
        g_Wsum_h[j] = __float2half(a + b);
        g_Wih_h[j]  = __float2half(a);
        g_Whh_h[j]  = __float2half(b);
    }
    for (int j = i0; j < 512 * 128; j += ns) g_W1h[j] = __float2half(W1[j]);
    for (int j = i0; j < 512 * 512; j += ns) {
        g_W2h[j]  = __float2half(W2[j]);
        g_W3h[j]  = __float2half(W3[j]);
        g_Wh1h[j] = __float2half(Wh1[j]);
        g_Wc1h[j] = __float2half(Wc1[j]);
        g_Wx1h[j] = __float2half(Wx1[j]);
    }
    for (int j = i0; j < 256 * 512; j += ns) {
        g_Wh2h[j] = __float2half(Wh2[j]);
        g_Wc2h[j] = __float2half(Wc2[j]);
        g_Wx2h[j] = __float2half(Wx2[j]);
    }
    for (int j = i0; j < BB * 128; j += ns) g_xh[j] = __float2half(x[j]);
    for (int j = i0; j < 1024; j += ns) g_rb[j] = rbih[j] + rbhh[j];
    for (int j = i0; j < 128; j += ns) g_pb[j] = pbih[j] + pbhh[j];
    for (int j = i0; j < BB * II; j += ns) {
        g_hp[0][j] = __float2half(0.f);
        g_hp[1][j] = __float2half(0.f);
    }
}

// ---------------- epilogue: softmax over 31 channels + sigmoid on last ---------
__global__ void __launch_bounds__(256)
out_kernel(float* __restrict__ out) {
    int gw = (blockIdx.x * blockDim.x + threadIdx.x) >> 5;
    int lane = threadIdx.x & 31;
    if (gw >= BB * LL) return;
    float v = g_y[gw * 32 + lane];
    float sv = (lane < 31) ? v : -3.0e38f;
    float mx = sv;
#pragma unroll
    for (int o = 16; o; o >>= 1) mx = fmaxf(mx, __shfl_xor_sync(0xffffffffu, mx, o));
    float e = (lane < 31) ? expf(sv - mx) : 0.f;
    float s = e;
#pragma unroll
    for (int o = 16; o; o >>= 1) s += __shfl_xor_sync(0xffffffffu, s, o);
    float r = (lane < 31) ? (e / s) : (1.f / (1.f + expf(-v)));
    out[gw * 32 + lane] = r;
}

// ---------------- launcher ----------------------------------------------------
extern "C" void kernel_launch(void* const* d_in, const int* in_sizes, int n_in,
                              void* d_out, int out_size) {
    const float* x    = (const float*)d_in[0];
    const float* W1   = (const float*)d_in[1];  const float* b1  = (const float*)d_in[2];
    const float* W2   = (const float*)d_in[3];  const float* b2  = (const float*)d_in[4];
    const float* W3   = (const float*)d_in[5];  const float* b3  = (const float*)d_in[6];
    const float* Wh1  = (const float*)d_in[7];  const float* bh1 = (const float*)d_in[8];
    const float* Wh2  = (const float*)d_in[9];  const float* bh2 = (const float*)d_in[10];
    const float* Wc1  = (const float*)d_in[11]; const float* bc1 = (const float*)d_in[12];
    const float* Wc2  = (const float*)d_in[13]; const float* bc2 = (const float*)d_in[14];
    const float* Wx1  = (const float*)d_in[15]; const float* bx1 = (const float*)d_in[16];
    const float* Wx2  = (const float*)d_in[17]; const float* bx2 = (const float*)d_in[18];
    const float* rWih = (const float*)d_in[19]; const float* rWhh = (const float*)d_in[20];
    const float* rbih = (const float*)d_in[21]; const float* rbhh = (const float*)d_in[22];
    const float* pWih = (const float*)d_in[23]; const float* pWhh = (const float*)d_in[24];
    const float* pbih = (const float*)d_in[25]; const float* pbhh = (const float*)d_in[26];
    float* out = (float*)d_out;

    cudaFuncSetAttribute(decode_kernel, cudaFuncAttributeMaxDynamicSharedMemorySize, DEC_SMEM);

    init_kernel<<<512, 256>>>(x, W1, W2, W3, Wh1, Wc1, Wx1, Wh2, Wc2, Wx2,
                              rWih, rWhh, rbih, rbhh, pbih, pbhh);

    // device symbol addresses for fp16 buffers
    __half *t0h, *t1h, *xh, *hb0, *x0h;
    __half *w1, *w2, *w3, *wh1, *wc1, *wx1, *wh2, *wc2, *wx2;
    float* cbuf;
    cudaGetSymbolAddress((void**)&t0h, g_t0h);
    cudaGetSymbolAddress((void**)&t1h, g_t1h);
    cudaGetSymbolAddress((void**)&xh,  g_xh);
    cudaGetSymbolAddress((void**)&hb0, g_hb);     // g_hb[0]
    cudaGetSymbolAddress((void**)&x0h, g_x0h);
    cudaGetSymbolAddress((void**)&cbuf, g_c);
    cudaGetSymbolAddress((void**)&w1,  g_W1h);
    cudaGetSymbolAddress((void**)&w2,  g_W2h);
    cudaGetSymbolAddress((void**)&w3,  g_W3h);
    cudaGetSymbolAddress((void**)&wh1, g_Wh1h);
    cudaGetSymbolAddress((void**)&wc1, g_Wc1h);
    cudaGetSymbolAddress((void**)&wx1, g_Wx1h);
    cudaGetSymbolAddress((void**)&wh2, g_Wh2h);
    cudaGetSymbolAddress((void**)&wc2, g_Wc2h);
    cudaGetSymbolAddress((void**)&wx2, g_Wx2h);

    dim3 blk(256);
    gemm_h<<<dim3(8, 16), blk>>>(xh,  w1,  b1,  t0h, NULL, 512, 128, 1);
    gemm_h<<<dim3(8, 16), blk>>>(t0h, w2,  b2,  t1h, NULL, 512, 512, 1);
    gemm_h<<<dim3(8, 16), blk>>>(t1h, w3,  b3,  t0h, NULL, 512, 512, 1);  // t3 -> t0h
    gemm_h<<<dim3(8, 16), blk>>>(t0h, wh1, bh1, t1h, NULL, 512, 512, 1);
    gemm_h<<<dim3(4, 16), blk>>>(t1h, wh2, bh2, hb0, NULL, 256, 512, 0);  // h0 (fp16)
    gemm_h<<<dim3(8, 16), blk>>>(t0h, wc1, bc1, t1h, NULL, 512, 512, 1);
    gemm_h<<<dim3(4, 16), blk>>>(t1h, wc2, bc2, NULL, cbuf, 256, 512, 0); // c0 (fp32)
    gemm_h<<<dim3(8, 16), blk>>>(t0h, wx1, bx1, t1h, NULL, 512, 512, 1);
    gemm_h<<<dim3(4, 16), blk>>>(t1h, wx2, bx2, x0h, NULL, 256, 512, 0);  // x0 (fp16)

    decode_kernel<<<NBLK, NTHR, DEC_SMEM>>>(pWih, pWhh);

    out_kernel<<<(BB * LL) / 8, 256>>>(out);
}

// round 9
// speedup vs baseline: 5.4520x; 1.2176x over previous
#include <cuda_runtime.h>
#include <cuda_fp16.h>
#include <math.h>
#include <stdint.h>

// Problem dims
#define BB 1024
#define HH 256
#define II 32
#define LL 128

#define NBLK 128
#define NTHR 512

// ---------------- device scratch ----------------------------------------------
__device__ __align__(16) __half g_Wsum_h[1024 * 256];  // fp16(rWih + rWhh)
__device__ __align__(16) __half g_Wih_h[1024 * 256];
__device__ __align__(16) __half g_Whh_h[1024 * 256];
__device__ __align__(16) __half g_hb[2][BB * HH];      // decode hidden ping-pong (fp16)
__device__ __align__(16) float  g_c[BB * HH];          // decode cell init (fp32)
__device__ __align__(16) __half g_x0h[BB * HH];
__device__ __align__(16) __half g_hp[2][BB * II];      // predictor hidden ping-pong
__device__ __align__(16) float  g_y[BB * LL * II];     // predictor outputs (fp32)
__device__ float g_rb[1024];
__device__ float g_pb[128];
__device__ unsigned g_count = 0;
__device__ unsigned g_gen = 0;
// fp16 activations + weights for the MLP front
__device__ __align__(16) __half g_xh[BB * 128];
__device__ __align__(16) __half g_t0h[BB * 512];
__device__ __align__(16) __half g_t1h[BB * 512];
__device__ __align__(16) __half g_th1[BB * 512];
__device__ __align__(16) __half g_tc1[BB * 512];
__device__ __align__(16) __half g_tx1[BB * 512];
__device__ __align__(16) __half g_W1h[512 * 128];
__device__ __align__(16) __half g_W2h[512 * 512];
__device__ __align__(16) __half g_W3h[512 * 512];
__device__ __align__(16) __half g_Wh1h[512 * 512];
__device__ __align__(16) __half g_Wc1h[512 * 512];
__device__ __align__(16) __half g_Wx1h[512 * 512];
__device__ __align__(16) __half g_Wh2h[256 * 512];
__device__ __align__(16) __half g_Wc2h[256 * 512];
__device__ __align__(16) __half g_Wx2h[256 * 512];

// ---------------- helpers ------------------------------------------------------
__device__ __forceinline__ uint32_t smem_u32(const void* p) {
    uint32_t a;
    asm("{ .reg .u64 t; cvta.to.shared.u64 t, %1; cvt.u32.u64 %0, t; }" : "=r"(a) : "l"(p));
    return a;
}
// fast nonlinearities (MUFU-based, ~1e-7 rel; saturate correctly at +-inf)
__device__ __forceinline__ float fsigm(float x) {
    return __fdividef(1.f, 1.f + __expf(-x));
}
__device__ __forceinline__ float ftanh(float x) {
    return 1.f - __fdividef(2.f, __expf(2.f * x) + 1.f);
}

// m16n8k16 fp16 mma, fp32 accum
__device__ __forceinline__ void mma16(float* c, const uint32_t* a, uint32_t b0, uint32_t b1) {
    asm volatile("mma.sync.aligned.m16n8k16.row.col.f32.f16.f16.f32 "
                 "{%0,%1,%2,%3}, {%4,%5,%6,%7}, {%8,%9}, {%0,%1,%2,%3};"
                 : "+f"(c[0]), "+f"(c[1]), "+f"(c[2]), "+f"(c[3])
                 : "r"(a[0]), "r"(a[1]), "r"(a[2]), "r"(a[3]), "r"(b0), "r"(b1));
}
__device__ __forceinline__ void ldsm4(uint32_t addr, uint32_t* r) {
    asm volatile("ldmatrix.sync.aligned.m8n8.x4.shared.b16 {%0,%1,%2,%3}, [%4];"
                 : "=r"(r[0]), "=r"(r[1]), "=r"(r[2]), "=r"(r[3]) : "r"(addr));
}
__device__ __forceinline__ void cp16(uint32_t d, const void* s) {
    asm volatile("cp.async.cg.shared.global [%0], [%1], 16;" :: "r"(d), "l"(s));
}
#define CP_COMMIT() asm volatile("cp.async.commit_group;" ::: "memory")
#define CP_WAIT(n)  asm volatile("cp.async.wait_group %0;" :: "n"(n) : "memory")

__device__ __forceinline__ uint32_t lds32(const __half* p) { return *reinterpret_cast<const uint32_t*>(p); }

// grid-wide software barrier
__device__ __forceinline__ void grid_sync() {
    __syncthreads();
    if (threadIdx.x == 0) {
        volatile unsigned* genp = &g_gen;
        unsigned gen = *genp;
        __threadfence();
        unsigned prev = atomicAdd(&g_count, 1u);
        if (prev == NBLK - 1) {
            g_count = 0;
            __threadfence();
            *genp = gen + 1;
        } else {
            while (*genp == gen) { __nanosleep(32); }
            __threadfence();
        }
    }
    __syncthreads();
}

// ---------------- decode SMEM layout (byte offsets; all regions disjoint) ------
#define DOFF_B    0          // [128][264]h weights (67584)
#define DOFF_A0   67584      // [64][136]h A half 0 (17408)
#define DOFF_A1   84992      // [64][136]h A half 1 (17408)
#define DOFF_G    102400     // [64][132]f gate exchange (33792)
#define DOFF_XS   136192     // [32][296]h predictor X (18944)
#define DOFF_P    155136     // [4][32][8]f predictor exchange (4096)
#define DOFF_BD   159232     // 128 f decode bias
#define DOFF_BP   159744     // 32 f predictor bias
#define DEC_SMEM  159872

// stage B: 128 gate rows x 256 halves into stride-264 smem (row n = g*32+hcl)
__device__ __forceinline__ void stage_Bh(__half* Bb, const __half* __restrict__ W,
                                         int nt8, int tid) {
#pragma unroll
    for (int i = 0; i < 8; ++i) {
        int e = tid + i * NTHR;
        int n = e >> 5, cb = (e & 31) * 8;
        int grow = (n >> 5) * 256 + nt8 * 32 + (n & 31);
        *reinterpret_cast<uint4*>(Bb + n * 264 + cb) =
            *reinterpret_cast<const uint4*>(W + grow * 256 + cb);
    }
}
// stage A half: 64 rows x 128 halves (src row stride 256) via cp.async
__device__ __forceinline__ void stage_A(uint32_t Abase, const __half* src, int kc0, int tid) {
#pragma unroll
    for (int i = 0; i < 2; ++i) {
        int e = tid + i * NTHR;
        int r = e >> 4, cb = (e & 15) * 8;
        cp16(Abase + (uint32_t)(r * 136 + cb) * 2u, src + r * 256 + kc0 + cb);
    }
}

// ---------------- persistent decode + predictor kernel -------------------------
__global__ void __launch_bounds__(NTHR, 1)
decode_kernel(const float* __restrict__ pWih, const float* __restrict__ pWhh) {
    extern __shared__ char sm[];
    const uint32_t sbase = smem_u32(sm);
    __half* Bb = (__half*)(sm + DOFF_B);
    float* G  = (float*)(sm + DOFF_G);
    float* P  = (float*)(sm + DOFF_P);
    float* biasD = (float*)(sm + DOFF_BD);
    float* biasP = (float*)(sm + DOFF_BP);

    const int bid = blockIdx.x;
    const int tid = threadIdx.x;
    const int wid = tid >> 5, lane = tid & 31;
    const int gid = lane >> 2, tig = lane & 3;
    const int wm = wid >> 3, wn = wid & 7;       // decode warp grid 2M x 8N
    // decode: 16 M-tiles(64 rows) x 8 col-tiles(32 hcols x 4 gates)
    const int mt = bid >> 3, nt8 = bid & 7;
    // predictor: 32 M-tiles(32 rows) x 4 col groups(8 icols)
    const int pm = bid >> 2, pic = bid & 3;
    const int pmt = (wid >> 2) & 1, png = wid & 3;  // warps 0..7

    // ldmatrix base addresses (bytes)
    const uint32_t aFragOff = (uint32_t)(((lane & 15) * 136 + (lane >> 4) * 8) * 2);
    const uint32_t aA0 = sbase + DOFF_A0 + (uint32_t)(wm * 32 * 136 * 2) + aFragOff;
    const uint32_t aA1 = sbase + DOFF_A1 + (uint32_t)(wm * 32 * 136 * 2) + aFragOff;
    const uint32_t aB  = sbase + DOFF_B +
        (uint32_t)(((wn * 16 + (lane >> 4) * 8 + (lane & 7)) * 264 + ((lane >> 3) & 1) * 8) * 2);
    const uint32_t xA  = sbase + DOFF_XS +
        (uint32_t)(((pmt * 16 + (lane & 15)) * 296 + (lane >> 4) * 8) * 2);

    // ---- one-time: biases, predictor B fragments (registers), B(rWih) ----
    if (tid < 128) biasD[tid] = g_rb[(tid >> 5) * 256 + nt8 * 32 + (tid & 31)];
    if (tid < 32)  biasP[tid] = g_pb[(tid >> 3) * 32 + pic * 8 + (tid & 7)];

    uint32_t pB[18][2];
    if (wid < 8) {
        const int prow = png * 32 + pic * 8 + gid;
#pragma unroll
        for (int ks = 0; ks < 18; ++ks) {
#pragma unroll
            for (int hh = 0; hh < 2; ++hh) {
                int k = ks * 16 + 2 * tig + hh * 8;
                float v0 = (k < 256) ? pWih[prow * 256 + k] : pWhh[prow * 32 + (k - 256)];
                float v1 = (k + 1 < 256) ? pWih[prow * 256 + k + 1] : pWhh[prow * 32 + (k + 1 - 256)];
                __half2 h2 = __floats2half2_rn(v0, v1);
                pB[ks][hh] = *reinterpret_cast<uint32_t*>(&h2);
            }
        }
    }

    // decode cell state: thread owns row rr = tid>>3 (64 rows), hcols (tid&7)*4..+4
    const int rr = tid >> 3, hq = (tid & 7) * 4;
    float creg[4];
    {
        float4 cv = *reinterpret_cast<const float4*>(g_c + (mt * 64 + rr) * 256 + nt8 * 32 + hq);
        creg[0] = cv.x; creg[1] = cv.y; creg[2] = cv.z; creg[3] = cv.w;
    }
    float cp_reg = 0.f;  // predictor cell (tid<256 threads own one cell)

    stage_Bh(Bb, g_Wih_h, nt8, tid);  // step-0 first B
    __syncthreads();

    float C[4][4];

    // mma over both staged A halves against current Bb
    auto mma_all = [&]() {
#pragma unroll
        for (int h = 0; h < 2; ++h) {
            const uint32_t ab = h ? aA1 : aA0;
            const uint32_t bb = aB + (uint32_t)(h * 256);
#pragma unroll
            for (int ks = 0; ks < 8; ++ks) {
                uint32_t a0[4], a1[4], b[4];
                ldsm4(ab + ks * 32, a0);
                ldsm4(ab + 4352 + ks * 32, a1);   // mf=1: +16 rows * 136h * 2B
                ldsm4(bb + ks * 32, b);
                mma16(C[0], a0, b[0], b[1]);
                mma16(C[1], a0, b[2], b[3]);
                mma16(C[2], a1, b[0], b[1]);
                mma16(C[3], a1, b[2], b[3]);
            }
        }
    };

    // epilogue: C frags -> G -> pointwise LSTM -> h[ob]
    auto epilogue = [&](int ob) {
#pragma unroll
        for (int mf = 0; mf < 2; ++mf)
#pragma unroll
            for (int nf = 0; nf < 2; ++nf) {
                int r = wm * 32 + mf * 16 + gid;
                int cl = wn * 16 + nf * 8 + 2 * tig;
                *reinterpret_cast<float2*>(&G[r * 132 + cl]) =
                    make_float2(C[mf * 2 + nf][0], C[mf * 2 + nf][1]);
                *reinterpret_cast<float2*>(&G[(r + 8) * 132 + cl]) =
                    make_float2(C[mf * 2 + nf][2], C[mf * 2 + nf][3]);
            }
        __syncthreads();
        float4 gi = *reinterpret_cast<const float4*>(&G[rr * 132 + hq]);
        float4 gf = *reinterpret_cast<const float4*>(&G[rr * 132 + 32 + hq]);
        float4 gg = *reinterpret_cast<const float4*>(&G[rr * 132 + 64 + hq]);
        float4 go = *reinterpret_cast<const float4*>(&G[rr * 132 + 96 + hq]);
        float4 bi = *reinterpret_cast<const float4*>(&biasD[hq]);
        float4 bf = *reinterpret_cast<const float4*>(&biasD[32 + hq]);
        float4 bg = *reinterpret_cast<const float4*>(&biasD[64 + hq]);
        float4 bo = *reinterpret_cast<const float4*>(&biasD[96 + hq]);
        float iv[4] = {gi.x + bi.x, gi.y + bi.y, gi.z + bi.z, gi.w + bi.w};
        float fv[4] = {gf.x + bf.x, gf.y + bf.y, gf.z + bf.z, gf.w + bf.w};
        float gv[4] = {gg.x + bg.x, gg.y + bg.y, gg.z + bg.z, gg.w + bg.w};
        float ov[4] = {go.x + bo.x, go.y + bo.y, go.z + bo.z, go.w + bo.w};
        __half hv[4];
#pragma unroll
        for (int j = 0; j < 4; ++j) {
            float cn = fsigm(fv[j]) * creg[j] + fsigm(iv[j]) * ftanh(gv[j]);
            creg[j] = cn;
            hv[j] = __float2half(fsigm(ov[j]) * ftanh(cn));
        }
        __half* dst = g_hb[ob] + (mt * 64 + rr) * 256 + nt8 * 32 + hq;
        *reinterpret_cast<__half2*>(dst)     = __halves2half2(hv[0], hv[1]);
        *reinterpret_cast<__half2*>(dst + 2) = __halves2half2(hv[2], hv[3]);
    };

    // stage predictor X = [h[ob] rows pm*32..+32 | hp[ib]] into Xs (cp.async)
    auto stage_Xs = [&](int ob, int ib) {
#pragma unroll
        for (int i = 0; i < 3; ++i) {
            int e = tid + i * NTHR;
            if (e < 1152) {
                int r = e / 36, ch = e % 36;
                const __half* src = (ch < 32)
                    ? (g_hb[ob] + (pm * 32 + r) * 256 + ch * 8)
                    : (g_hp[ib] + (pm * 32 + r) * 32 + (ch - 32) * 8);
                cp16(sbase + DOFF_XS + (uint32_t)(r * 296 + ch * 8) * 2u, src);
            }
        }
    };

    // predictor step t (after Xs staged + synced)
    auto predictor = [&](int t, int ib, int ob) {
        if (wid < 8) {
            float pc[4] = {0.f, 0.f, 0.f, 0.f};
#pragma unroll
            for (int ks = 0; ks < 18; ++ks) {
                uint32_t a[4];
                ldsm4(xA + ks * 32, a);
                mma16(pc, a, pB[ks][0], pB[ks][1]);
            }
            int ml = pmt * 16 + gid;
            *reinterpret_cast<float2*>(&P[(png * 32 + ml) * 8 + 2 * tig]) =
                make_float2(pc[0], pc[1]);
            *reinterpret_cast<float2*>(&P[(png * 32 + ml + 8) * 8 + 2 * tig]) =
                make_float2(pc[2], pc[3]);
        }
        __syncthreads();
        if (tid < 256) {
            int ml = tid >> 3, ic = tid & 7;
            float iv = P[(0  + ml) * 8 + ic] + biasP[ic];
            float fv = P[(32 + ml) * 8 + ic] + biasP[8 + ic];
            float gv = P[(64 + ml) * 8 + ic] + biasP[16 + ic];
            float ov = P[(96 + ml) * 8 + ic] + biasP[24 + ic];
            float cn = fsigm(fv) * cp_reg + fsigm(iv) * ftanh(gv);
            cp_reg = cn;
            float hn = fsigm(ov) * ftanh(cn);
            int m = pm * 32 + ml, icol = pic * 8 + ic;
            g_hp[ob][m * 32 + icol] = __float2half(hn);
            g_y[(m * LL + t) * II + icol] = hn;
        }
    };

    // ================= step 0 (two B matrices: rWih then rWhh) =================
#pragma unroll
    for (int i = 0; i < 4; ++i)
#pragma unroll
        for (int j = 0; j < 4; ++j) C[i][j] = 0.f;

    stage_A(sbase + DOFF_A0, g_x0h + mt * 64 * 256, 0, tid);   CP_COMMIT();
    stage_A(sbase + DOFF_A1, g_x0h + mt * 64 * 256, 128, tid); CP_COMMIT();
    CP_WAIT(0); __syncthreads();
    mma_all();
    __syncthreads();
    stage_Bh(Bb, g_Whh_h, nt8, tid); __syncthreads();
    stage_A(sbase + DOFF_A0, g_hb[0] + mt * 64 * 256, 0, tid);   CP_COMMIT();
    stage_A(sbase + DOFF_A1, g_hb[0] + mt * 64 * 256, 128, tid); CP_COMMIT();
    CP_WAIT(0); __syncthreads();
    mma_all();
    __syncthreads();
    stage_Bh(Bb, g_Wsum_h, nt8, tid);   // steady-state weights (synced via grid_sync)
    epilogue(1);
    grid_sync();
    // tail of step 0: prefetch A for step 1, stage+run predictor 0
    stage_Xs(1, 0); CP_COMMIT();
    stage_A(sbase + DOFF_A0, g_hb[1] + mt * 64 * 256, 0, tid);   CP_COMMIT();
    stage_A(sbase + DOFF_A1, g_hb[1] + mt * 64 * 256, 128, tid); CP_COMMIT();
    CP_WAIT(2); __syncthreads();
    predictor(0, 0, 1);

    // ================= steady-state steps 1..127 =================
    for (int t = 1; t < LL; ++t) {
        const int ib = t & 1, ob = ib ^ 1;

        CP_WAIT(0); __syncthreads();   // A halves (staged in previous tail) ready
#pragma unroll
        for (int i = 0; i < 4; ++i)
#pragma unroll
            for (int j = 0; j < 4; ++j) C[i][j] = 0.f;
        mma_all();
        epilogue(ob);
        grid_sync();

        // tail: prefetch next A + predictor t (overlapped with cp.async)
        stage_Xs(ob, ib); CP_COMMIT();
        if (t < LL - 1) {
            stage_A(sbase + DOFF_A0, g_hb[ob] + mt * 64 * 256, 0, tid);   CP_COMMIT();
            stage_A(sbase + DOFF_A1, g_hb[ob] + mt * 64 * 256, 128, tid); CP_COMMIT();
            CP_WAIT(2);
        } else {
            CP_WAIT(0);
        }
        __syncthreads();
        predictor(t, ib, ob);
        __syncthreads();
    }
}

// ---------------- fp16 tensor GEMM (3-way batched over blockIdx.z) -------------
__global__ void __launch_bounds__(256, 2)
gemm_h(const __half* __restrict__ Aa, const __half* __restrict__ Ab_, const __half* __restrict__ Ac,
       const __half* __restrict__ Wa, const __half* __restrict__ Wb, const __half* __restrict__ Wc,
       const float* __restrict__ ba, const float* __restrict__ bb, const float* __restrict__ bc,
       __half* Cha, __half* Chb, __half* Chc,
       float* Cfa, float* Cfb, float* Cfc,
       int N, int K, int act) {
    __shared__ __half As[64 * 72];
    __shared__ __half Bs[64 * 72];
    const int z = blockIdx.z;
    const __half* A = (z == 0) ? Aa : (z == 1) ? Ab_ : Ac;
    const __half* W = (z == 0) ? Wa : (z == 1) ? Wb : Wc;
    const float* bias = (z == 0) ? ba : (z == 1) ? bb : bc;
    __half* Ch = (z == 0) ? Cha : (z == 1) ? Chb : Chc;
    float* Cf = (z == 0) ? Cfa : (z == 1) ? Cfb : Cfc;

    const int tid = threadIdx.x;
    const int wid = tid >> 5, lane = tid & 31;
    const int gid = lane >> 2, tig = lane & 3;
    const int wm = wid >> 2, wn = wid & 3;       // 2M x 4N warp grid, warp 32x16
    const int m0 = blockIdx.y * 64, n0 = blockIdx.x * 64;

    const uint32_t sA = smem_u32(As), sB = smem_u32(Bs);
    const uint32_t aFrag = sA + (uint32_t)(((wm * 32 + (lane & 15)) * 72 + (lane >> 4) * 8) * 2);
    const uint32_t bFrag = sB + (uint32_t)(((wn * 16 + (lane >> 4) * 8 + (lane & 7)) * 72 +
                                            ((lane >> 3) & 1) * 8) * 2);

    float C[4][4];
#pragma unroll
    for (int i = 0; i < 4; ++i)
#pragma unroll
        for (int j = 0; j < 4; ++j) C[i][j] = 0.f;

    for (int kk = 0; kk < K; kk += 64) {
        {
            int r = tid >> 2, cb = (tid & 3) * 16;
            *reinterpret_cast<uint4*>(As + r * 72 + cb) =
                *reinterpret_cast<const uint4*>(A + (m0 + r) * K + kk + cb);
            *reinterpret_cast<uint4*>(As + r * 72 + cb + 8) =
                *reinterpret_cast<const uint4*>(A + (m0 + r) * K + kk + cb + 8);
            *reinterpret_cast<uint4*>(Bs + r * 72 + cb) =
                *reinterpret_cast<const uint4*>(W + (n0 + r) * K + kk + cb);
            *reinterpret_cast<uint4*>(Bs + r * 72 + cb + 8) =
                *reinterpret_cast<const uint4*>(W + (n0 + r) * K + kk + cb + 8);
        }
        __syncthreads();
#pragma unroll
        for (int ks = 0; ks < 4; ++ks) {
            uint32_t a0[4], a1[4], b[4];
            ldsm4(aFrag + ks * 32, a0);
            ldsm4(aFrag + 16 * 72 * 2 + ks * 32, a1);
            ldsm4(bFrag + ks * 32, b);
            mma16(C[0], a0, b[0], b[1]);
            mma16(C[1], a0, b[2], b[3]);
            mma16(C[2], a1, b[0], b[1]);
            mma16(C[3], a1, b[2], b[3]);
        }
        __syncthreads();
    }

#pragma unroll
    for (int mf = 0; mf < 2; ++mf)
#pragma unroll
        for (int nf = 0; nf < 2; ++nf) {
            int r = m0 + wm * 32 + mf * 16 + gid;
            int c = n0 + wn * 16 + nf * 8 + 2 * tig;
            float b0 = bias[c], b1 = bias[c + 1];
            float v0 = C[mf * 2 + nf][0] + b0, v1 = C[mf * 2 + nf][1] + b1;
            float v2 = C[mf * 2 + nf][2] + b0, v3 = C[mf * 2 + nf][3] + b1;
            if (act) {
                v0 = v0 >= 0.f ? v0 : 0.2f * v0;
                v1 = v1 >= 0.f ? v1 : 0.2f * v1;
                v2 = v2 >= 0.f ? v2 : 0.2f * v2;
                v3 = v3 >= 0.f ? v3 : 0.2f * v3;
            }
            if (Ch) {
                *reinterpret_cast<__half2*>(Ch + r * N + c)       = __floats2half2_rn(v0, v1);
                *reinterpret_cast<__half2*>(Ch + (r + 8) * N + c) = __floats2half2_rn(v2, v3);
            } else {
                *reinterpret_cast<float2*>(Cf + r * N + c)       = make_float2(v0, v1);
                *reinterpret_cast<float2*>(Cf + (r + 8) * N + c) = make_float2(v2, v3);
            }
        }
}

// ---------------- init: convert weights/activations to fp16, sums, zeros -------
__global__ void init_kernel(const float* x, const float* W1, const float* W2, const float* W3,
                            const float* Wh1, const float* Wc1, const float* Wx1,
                            const float* Wh2, const float* Wc2, const float* Wx2,
                            const float* rWih, const float* rWhh,
                            const float* rbih, const float* rbhh,
                            const float* pbih, const float* pbhh) {
    const int i0 = blockIdx.x * blockDim.x + threadIdx.x;
    const int ns = gridDim.x * blockDim.x;
    for (int j = i0; j < 1024 * 256; j += ns) {
        float a = rWih[j], b = rWhh[j];
        g_Wsum_h[j] = __float2half(a + b);
        g_Wih_h[j]  = __float2half(a);
        g_Whh_h[j]  = __float2half(b);
    }
    for (int j = i0; j < 512 * 128; j += ns) g_W1h[j] = __float2half(W1[j]);
    for (int j = i0; j < 512 * 512; j += ns) {
        g_W2h[j]  = __float2half(W2[j]);
        g_W3h[j]  = __float2half(W3[j]);
        g_Wh1h[j] = __float2half(Wh1[j]);
        g_Wc1h[j] = __float2half(Wc1[j]);
        g_Wx1h[j] = __float2half(Wx1[j]);
    }
    for (int j = i0; j < 256 * 512; j += ns) {
        g_Wh2h[j] = __float2half(Wh2[j]);
        g_Wc2h[j] = __float2half(Wc2[j]);
        g_Wx2h[j] = __float2half(Wx2[j]);
    }
    for (int j = i0; j < BB * 128; j += ns) g_xh[j] = __float2half(x[j]);
    for (int j = i0; j < 1024; j += ns) g_rb[j] = rbih[j] + rbhh[j];
    for (int j = i0; j < 128; j += ns) g_pb[j] = pbih[j] + pbhh[j];
    for (int j = i0; j < BB * II; j += ns) {
        g_hp[0][j] = __float2half(0.f);
        g_hp[1][j] = __float2half(0.f);
    }
}

// ---------------- epilogue: softmax over 31 channels + sigmoid on last ---------
__global__ void __launch_bounds__(256)
out_kernel(float* __restrict__ out) {
    int gw = (blockIdx.x * blockDim.x + threadIdx.x) >> 5;
    int lane = threadIdx.x & 31;
    if (gw >= BB * LL) return;
    float v = g_y[gw * 32 + lane];
    float sv = (lane < 31) ? v : -3.0e38f;
    float mx = sv;
#pragma unroll
    for (int o = 16; o; o >>= 1) mx = fmaxf(mx, __shfl_xor_sync(0xffffffffu, mx, o));
    float e = (lane < 31) ? expf(sv - mx) : 0.f;
    float s = e;
#pragma unroll
    for (int o = 16; o; o >>= 1) s += __shfl_xor_sync(0xffffffffu, s, o);
    float r = (lane < 31) ? (e / s) : (1.f / (1.f + expf(-v)));
    out[gw * 32 + lane] = r;
}

// ---------------- launcher ----------------------------------------------------
extern "C" void kernel_launch(void* const* d_in, const int* in_sizes, int n_in,
                              void* d_out, int out_size) {
    const float* x    = (const float*)d_in[0];
    const float* W1   = (const float*)d_in[1];  const float* b1  = (const float*)d_in[2];
    const float* W2   = (const float*)d_in[3];  const float* b2  = (const float*)d_in[4];
    const float* W3   = (const float*)d_in[5];  const float* b3  = (const float*)d_in[6];
    const float* Wh1  = (const float*)d_in[7];  const float* bh1 = (const float*)d_in[8];
    const float* Wh2  = (const float*)d_in[9];  const float* bh2 = (const float*)d_in[10];
    const float* Wc1  = (const float*)d_in[11]; const float* bc1 = (const float*)d_in[12];
    const float* Wc2  = (const float*)d_in[13]; const float* bc2 = (const float*)d_in[14];
    const float* Wx1  = (const float*)d_in[15]; const float* bx1 = (const float*)d_in[16];
    const float* Wx2  = (const float*)d_in[17]; const float* bx2 = (const float*)d_in[18];
    const float* rWih = (const float*)d_in[19]; const float* rWhh = (const float*)d_in[20];
    const float* rbih = (const float*)d_in[21]; const float* rbhh = (const float*)d_in[22];
    const float* pWih = (const float*)d_in[23]; const float* pWhh = (const float*)d_in[24];
    const float* pbih = (const float*)d_in[25]; const float* pbhh = (const float*)d_in[26];
    float* out = (float*)d_out;

    cudaFuncSetAttribute(decode_kernel, cudaFuncAttributeMaxDynamicSharedMemorySize, DEC_SMEM);

    init_kernel<<<512, 256>>>(x, W1, W2, W3, Wh1, Wc1, Wx1, Wh2, Wc2, Wx2,
                              rWih, rWhh, rbih, rbhh, pbih, pbhh);

    __half *t0h, *t1h, *xh, *hb0, *x0h, *th1, *tc1, *tx1;
    __half *w1, *w2, *w3, *wh1, *wc1, *wx1, *wh2, *wc2, *wx2;
    float* cbuf;
    cudaGetSymbolAddress((void**)&t0h, g_t0h);
    cudaGetSymbolAddress((void**)&t1h, g_t1h);
    cudaGetSymbolAddress((void**)&xh,  g_xh);
    cudaGetSymbolAddress((void**)&hb0, g_hb);     // g_hb[0]
    cudaGetSymbolAddress((void**)&x0h, g_x0h);
    cudaGetSymbolAddress((void**)&th1, g_th1);
    cudaGetSymbolAddress((void**)&tc1, g_tc1);
    cudaGetSymbolAddress((void**)&tx1, g_tx1);
    cudaGetSymbolAddress((void**)&cbuf, g_c);
    cudaGetSymbolAddress((void**)&w1,  g_W1h);
    cudaGetSymbolAddress((void**)&w2,  g_W2h);
    cudaGetSymbolAddress((void**)&w3,  g_W3h);
    cudaGetSymbolAddress((void**)&wh1, g_Wh1h);
    cudaGetSymbolAddress((void**)&wc1, g_Wc1h);
    cudaGetSymbolAddress((void**)&wx1, g_Wx1h);
    cudaGetSymbolAddress((void**)&wh2, g_Wh2h);
    cudaGetSymbolAddress((void**)&wc2, g_Wc2h);
    cudaGetSymbolAddress((void**)&wx2, g_Wx2h);

    dim3 blk(256);
    // L1..L3 (single, z=1)
    gemm_h<<<dim3(8, 16, 1), blk>>>(xh, xh, xh, w1, w1, w1, b1, b1, b1,
                                    t0h, NULL, NULL, NULL, NULL, NULL, 512, 128, 1);
    gemm_h<<<dim3(8, 16, 1), blk>>>(t0h, t0h, t0h, w2, w2, w2, b2, b2, b2,
                                    t1h, NULL, NULL, NULL, NULL, NULL, 512, 512, 1);
    gemm_h<<<dim3(8, 16, 1), blk>>>(t1h, t1h, t1h, w3, w3, w3, b3, b3, b3,
                                    t0h, NULL, NULL, NULL, NULL, NULL, 512, 512, 1);
    // heads layer 1 (batched z=3): t3 -> th1/tc1/tx1
    gemm_h<<<dim3(8, 16, 3), blk>>>(t0h, t0h, t0h, wh1, wc1, wx1, bh1, bc1, bx1,
                                    th1, tc1, tx1, NULL, NULL, NULL, 512, 512, 1);
    // heads layer 2 (batched z=3): -> h0 (fp16), c0 (fp32), x0 (fp16)
    gemm_h<<<dim3(4, 16, 3), blk>>>(th1, tc1, tx1, wh2, wc2, wx2, bh2, bc2, bx2,
                                    hb0, NULL, x0h, NULL, cbuf, NULL, 256, 512, 0);

    decode_kernel<<<NBLK, NTHR, DEC_SMEM>>>(pWih, pWhh);

    out_kernel<<<(BB * LL) / 8, 256>>>(out);
}

// round 10
// speedup vs baseline: 6.6494x; 1.2196x over previous
#include <cuda_runtime.h>
#include <cuda_fp16.h>
#include <math.h>
#include <stdint.h>

// Problem dims
#define BB 1024
#define HH 256
#define II 32
#define LL 128

#define NBLK 128
#define NTHR 512

// ---------------- device scratch ----------------------------------------------
__device__ __align__(16) __half g_Wsum_h[1024 * 256];  // fp16(rWih + rWhh)
__device__ __align__(16) __half g_Wih_h[1024 * 256];
__device__ __align__(16) __half g_Whh_h[1024 * 256];
__device__ __align__(16) __half g_hb[2][BB * HH];      // decode hidden ping-pong (fp16)
__device__ __align__(16) float  g_c[BB * HH];          // decode cell init (fp32)
__device__ __align__(16) __half g_x0h[BB * HH];
__device__ __align__(16) __half g_hp[2][BB * II];      // predictor hidden ping-pong
__device__ __align__(16) float  g_y[BB * LL * II];     // predictor outputs (fp32)
__device__ float g_rb[1024];
__device__ float g_pb[128];
__device__ unsigned g_gcnt[16 * 32];                   // per-group barrier counters (128B lines)
// fp16 activations + weights for the MLP front
__device__ __align__(16) __half g_xh[BB * 128];
__device__ __align__(16) __half g_t0h[BB * 512];
__device__ __align__(16) __half g_t1h[BB * 512];
__device__ __align__(16) __half g_th1[BB * 512];
__device__ __align__(16) __half g_tc1[BB * 512];
__device__ __align__(16) __half g_tx1[BB * 512];
__device__ __align__(16) __half g_W1h[512 * 128];
__device__ __align__(16) __half g_W2h[512 * 512];
__device__ __align__(16) __half g_W3h[512 * 512];
__device__ __align__(16) __half g_Wh1h[512 * 512];
__device__ __align__(16) __half g_Wc1h[512 * 512];
__device__ __align__(16) __half g_Wx1h[512 * 512];
__device__ __align__(16) __half g_Wh2h[256 * 512];
__device__ __align__(16) __half g_Wc2h[256 * 512];
__device__ __align__(16) __half g_Wx2h[256 * 512];

// ---------------- helpers ------------------------------------------------------
__device__ __forceinline__ uint32_t smem_u32(const void* p) {
    uint32_t a;
    asm("{ .reg .u64 t; cvta.to.shared.u64 t, %1; cvt.u32.u64 %0, t; }" : "=r"(a) : "l"(p));
    return a;
}
__device__ __forceinline__ float fsigm(float x) {
    return __fdividef(1.f, 1.f + __expf(-x));
}
__device__ __forceinline__ float ftanh(float x) {
    return 1.f - __fdividef(2.f, __expf(2.f * x) + 1.f);
}
__device__ __forceinline__ unsigned ldcg_u32(const unsigned* p) {
    unsigned v;
    asm volatile("ld.global.cg.u32 %0, [%1];" : "=r"(v) : "l"(p) : "memory");
    return v;
}

// m16n8k16 fp16 mma, fp32 accum
__device__ __forceinline__ void mma16(float* c, const uint32_t* a, uint32_t b0, uint32_t b1) {
    asm volatile("mma.sync.aligned.m16n8k16.row.col.f32.f16.f16.f32 "
                 "{%0,%1,%2,%3}, {%4,%5,%6,%7}, {%8,%9}, {%0,%1,%2,%3};"
                 : "+f"(c[0]), "+f"(c[1]), "+f"(c[2]), "+f"(c[3])
                 : "r"(a[0]), "r"(a[1]), "r"(a[2]), "r"(a[3]), "r"(b0), "r"(b1));
}
__device__ __forceinline__ void ldsm4(uint32_t addr, uint32_t* r) {
    asm volatile("ldmatrix.sync.aligned.m8n8.x4.shared.b16 {%0,%1,%2,%3}, [%4];"
                 : "=r"(r[0]), "=r"(r[1]), "=r"(r[2]), "=r"(r[3]) : "r"(addr));
}
__device__ __forceinline__ void cp16(uint32_t d, const void* s) {
    asm volatile("cp.async.cg.shared.global [%0], [%1], 16;" :: "r"(d), "l"(s));
}
#define CP_COMMIT() asm volatile("cp.async.commit_group;" ::: "memory")
#define CP_WAIT(n)  asm volatile("cp.async.wait_group %0;" :: "n"(n) : "memory")

// 8-CTA group barrier: monotonic counter, no leader, no generation reset.
__device__ __forceinline__ void group_sync(int grp, unsigned target) {
    __syncthreads();
    if (threadIdx.x == 0) {
        unsigned* cnt = &g_gcnt[grp * 32];
        __threadfence();
        atomicAdd(cnt, 1u);
        while (ldcg_u32(cnt) < target) { }
        __threadfence();
    }
    __syncthreads();
}

// ---------------- decode SMEM layout (byte offsets; all regions disjoint) ------
#define DOFF_B    0          // [128][264]h weights (67584)
#define DOFF_A0   67584      // [64][136]h A half 0 (17408)
#define DOFF_A1   84992      // [64][136]h A half 1 (17408)
#define DOFF_G    102400     // [64][132]f gate exchange (33792)
#define DOFF_XS   136192     // [32][296]h predictor X (18944)
#define DOFF_P    155136     // [4][32][8]f predictor exchange (4096)
#define DOFF_BD   159232     // 128 f decode bias
#define DOFF_BP   159744     // 32 f predictor bias
#define DEC_SMEM  159872

// stage B: 128 gate rows x 256 halves into stride-264 smem (row n = g*32+hcl)
__device__ __forceinline__ void stage_Bh(__half* Bb, const __half* __restrict__ W,
                                         int nt8, int tid) {
#pragma unroll
    for (int i = 0; i < 8; ++i) {
        int e = tid + i * NTHR;
        int n = e >> 5, cb = (e & 31) * 8;
        int grow = (n >> 5) * 256 + nt8 * 32 + (n & 31);
        *reinterpret_cast<uint4*>(Bb + n * 264 + cb) =
            *reinterpret_cast<const uint4*>(W + grow * 256 + cb);
    }
}
// stage A half: 64 rows x 128 halves (src row stride 256) via cp.async
__device__ __forceinline__ void stage_A(uint32_t Abase, const __half* src, int kc0, int tid) {
#pragma unroll
    for (int i = 0; i < 2; ++i) {
        int e = tid + i * NTHR;
        int r = e >> 4, cb = (e & 15) * 8;
        cp16(Abase + (uint32_t)(r * 136 + cb) * 2u, src + r * 256 + kc0 + cb);
    }
}

// ---------------- persistent decode + predictor kernel -------------------------
__global__ void __launch_bounds__(NTHR, 1)
decode_kernel(const float* __restrict__ pWih, const float* __restrict__ pWhh) {
    extern __shared__ char sm[];
    const uint32_t sbase = smem_u32(sm);
    __half* Bb = (__half*)(sm + DOFF_B);
    float* G  = (float*)(sm + DOFF_G);
    float* P  = (float*)(sm + DOFF_P);
    float* biasD = (float*)(sm + DOFF_BD);
    float* biasP = (float*)(sm + DOFF_BP);

    const int bid = blockIdx.x;
    const int tid = threadIdx.x;
    const int wid = tid >> 5, lane = tid & 31;
    const int gid = lane >> 2, tig = lane & 3;
    const int wm = wid >> 3, wn = wid & 7;       // decode warp grid 2M x 8N
    // decode: 16 M-tiles(64 rows) x 8 col-tiles(32 hcols x 4 gates)
    const int mt = bid >> 3, nt8 = bid & 7;
    // predictor role REMAPPED into the same 8-CTA group (group = mt):
    //   rows pm*32 ⊂ mt*64..+64, so all step deps stay inside the group.
    const int pm = mt * 2 + (nt8 >> 2), pic = nt8 & 3;
    const int pmt = (wid >> 2) & 1, png = wid & 3;  // warps 0..7

    // ldmatrix base addresses (bytes)
    const uint32_t aFragOff = (uint32_t)(((lane & 15) * 136 + (lane >> 4) * 8) * 2);
    const uint32_t aA0 = sbase + DOFF_A0 + (uint32_t)(wm * 32 * 136 * 2) + aFragOff;
    const uint32_t aA1 = sbase + DOFF_A1 + (uint32_t)(wm * 32 * 136 * 2) + aFragOff;
    const uint32_t aB  = sbase + DOFF_B +
        (uint32_t)(((wn * 16 + (lane >> 4) * 8 + (lane & 7)) * 264 + ((lane >> 3) & 1) * 8) * 2);
    const uint32_t xA  = sbase + DOFF_XS +
        (uint32_t)(((pmt * 16 + (lane & 15)) * 296 + (lane >> 4) * 8) * 2);

    // ---- one-time: biases, predictor B fragments (registers), B(rWih) ----
    if (tid < 128) biasD[tid] = g_rb[(tid >> 5) * 256 + nt8 * 32 + (tid & 31)];
    if (tid < 32)  biasP[tid] = g_pb[(tid >> 3) * 32 + pic * 8 + (tid & 7)];

    uint32_t pB[18][2];
    if (wid < 8) {
        const int prow = png * 32 + pic * 8 + gid;
#pragma unroll
        for (int ks = 0; ks < 18; ++ks) {
#pragma unroll
            for (int hh = 0; hh < 2; ++hh) {
                int k = ks * 16 + 2 * tig + hh * 8;
                float v0 = (k < 256) ? pWih[prow * 256 + k] : pWhh[prow * 32 + (k - 256)];
                float v1 = (k + 1 < 256) ? pWih[prow * 256 + k + 1] : pWhh[prow * 32 + (k + 1 - 256)];
                __half2 h2 = __floats2half2_rn(v0, v1);
                pB[ks][hh] = *reinterpret_cast<uint32_t*>(&h2);
            }
        }
    }

    // decode cell state: thread owns row rr = tid>>3 (64 rows), hcols (tid&7)*4..+4
    const int rr = tid >> 3, hq = (tid & 7) * 4;
    float creg[4];
    {
        float4 cv = *reinterpret_cast<const float4*>(g_c + (mt * 64 + rr) * 256 + nt8 * 32 + hq);
        creg[0] = cv.x; creg[1] = cv.y; creg[2] = cv.z; creg[3] = cv.w;
    }
    float cp_reg = 0.f;  // predictor cell (tid<256 threads own one cell)

    stage_Bh(Bb, g_Wih_h, nt8, tid);  // step-0 first B
    __syncthreads();

    float C[4][4];
    unsigned btarget = 8;   // group barrier target (monotonic, +8 per step)

    // mma over both staged A halves against current Bb
    auto mma_all = [&]() {
#pragma unroll
        for (int h = 0; h < 2; ++h) {
            const uint32_t ab = h ? aA1 : aA0;
            const uint32_t bb = aB + (uint32_t)(h * 256);
#pragma unroll
            for (int ks = 0; ks < 8; ++ks) {
                uint32_t a0[4], a1[4], b[4];
                ldsm4(ab + ks * 32, a0);
                ldsm4(ab + 4352 + ks * 32, a1);   // mf=1: +16 rows * 136h * 2B
                ldsm4(bb + ks * 32, b);
                mma16(C[0], a0, b[0], b[1]);
                mma16(C[1], a0, b[2], b[3]);
                mma16(C[2], a1, b[0], b[1]);
                mma16(C[3], a1, b[2], b[3]);
            }
        }
    };

    // epilogue: C frags -> G -> pointwise LSTM -> h[ob]
    auto epilogue = [&](int ob) {
#pragma unroll
        for (int mf = 0; mf < 2; ++mf)
#pragma unroll
            for (int nf = 0; nf < 2; ++nf) {
                int r = wm * 32 + mf * 16 + gid;
                int cl = wn * 16 + nf * 8 + 2 * tig;
                *reinterpret_cast<float2*>(&G[r * 132 + cl]) =
                    make_float2(C[mf * 2 + nf][0], C[mf * 2 + nf][1]);
                *reinterpret_cast<float2*>(&G[(r + 8) * 132 + cl]) =
                    make_float2(C[mf * 2 + nf][2], C[mf * 2 + nf][3]);
            }
        __syncthreads();
        float4 gi = *reinterpret_cast<const float4*>(&G[rr * 132 + hq]);
        float4 gf = *reinterpret_cast<const float4*>(&G[rr * 132 + 32 + hq]);
        float4 gg = *reinterpret_cast<const float4*>(&G[rr * 132 + 64 + hq]);
        float4 go = *reinterpret_cast<const float4*>(&G[rr * 132 + 96 + hq]);
        float4 bi = *reinterpret_cast<const float4*>(&biasD[hq]);
        float4 bf = *reinterpret_cast<const float4*>(&biasD[32 + hq]);
        float4 bg = *reinterpret_cast<const float4*>(&biasD[64 + hq]);
        float4 bo = *reinterpret_cast<const float4*>(&biasD[96 + hq]);
        float iv[4] = {gi.x + bi.x, gi.y + bi.y, gi.z + bi.z, gi.w + bi.w};
        float fv[4] = {gf.x + bf.x, gf.y + bf.y, gf.z + bf.z, gf.w + bf.w};
        float gv[4] = {gg.x + bg.x, gg.y + bg.y, gg.z + bg.z, gg.w + bg.w};
        float ov[4] = {go.x + bo.x, go.y + bo.y, go.z + bo.z, go.w + bo.w};
        __half hv[4];
#pragma unroll
        for (int j = 0; j < 4; ++j) {
            float cn = fsigm(fv[j]) * creg[j] + fsigm(iv[j]) * ftanh(gv[j]);
            creg[j] = cn;
            hv[j] = __float2half(fsigm(ov[j]) * ftanh(cn));
        }
        __half* dst = g_hb[ob] + (mt * 64 + rr) * 256 + nt8 * 32 + hq;
        *reinterpret_cast<__half2*>(dst)     = __halves2half2(hv[0], hv[1]);
        *reinterpret_cast<__half2*>(dst + 2) = __halves2half2(hv[2], hv[3]);
    };

    // stage predictor X = [h[ob] rows pm*32..+32 | hp[ib]] into Xs (cp.async)
    auto stage_Xs = [&](int ob, int ib) {
#pragma unroll
        for (int i = 0; i < 3; ++i) {
            int e = tid + i * NTHR;
            if (e < 1152) {
                int r = e / 36, ch = e % 36;
                const __half* src = (ch < 32)
                    ? (g_hb[ob] + (pm * 32 + r) * 256 + ch * 8)
                    : (g_hp[ib] + (pm * 32 + r) * 32 + (ch - 32) * 8);
                cp16(sbase + DOFF_XS + (uint32_t)(r * 296 + ch * 8) * 2u, src);
            }
        }
    };

    // predictor step t (after Xs staged + synced)
    auto predictor = [&](int t, int ob) {
        if (wid < 8) {
            float pc[4] = {0.f, 0.f, 0.f, 0.f};
#pragma unroll
            for (int ks = 0; ks < 18; ++ks) {
                uint32_t a[4];
                ldsm4(xA + ks * 32, a);
                mma16(pc, a, pB[ks][0], pB[ks][1]);
            }
            int ml = pmt * 16 + gid;
            *reinterpret_cast<float2*>(&P[(png * 32 + ml) * 8 + 2 * tig]) =
                make_float2(pc[0], pc[1]);
            *reinterpret_cast<float2*>(&P[(png * 32 + ml + 8) * 8 + 2 * tig]) =
                make_float2(pc[2], pc[3]);
        }
        __syncthreads();
        if (tid < 256) {
            int ml = tid >> 3, ic = tid & 7;
            float iv = P[(0  + ml) * 8 + ic] + biasP[ic];
            float fv = P[(32 + ml) * 8 + ic] + biasP[8 + ic];
            float gv = P[(64 + ml) * 8 + ic] + biasP[16 + ic];
            float ov = P[(96 + ml) * 8 + ic] + biasP[24 + ic];
            float cn = fsigm(fv) * cp_reg + fsigm(iv) * ftanh(gv);
            cp_reg = cn;
            float hn = fsigm(ov) * ftanh(cn);
            int m = pm * 32 + ml, icol = pic * 8 + ic;
            g_hp[ob][m * 32 + icol] = __float2half(hn);
            g_y[(m * LL + t) * II + icol] = hn;
        }
    };

    // ================= step 0 (two B matrices: rWih then rWhh) =================
#pragma unroll
    for (int i = 0; i < 4; ++i)
#pragma unroll
        for (int j = 0; j < 4; ++j) C[i][j] = 0.f;

    stage_A(sbase + DOFF_A0, g_x0h + mt * 64 * 256, 0, tid);   CP_COMMIT();
    stage_A(sbase + DOFF_A1, g_x0h + mt * 64 * 256, 128, tid); CP_COMMIT();
    CP_WAIT(0); __syncthreads();
    mma_all();
    __syncthreads();
    stage_Bh(Bb, g_Whh_h, nt8, tid); __syncthreads();
    stage_A(sbase + DOFF_A0, g_hb[0] + mt * 64 * 256, 0, tid);   CP_COMMIT();
    stage_A(sbase + DOFF_A1, g_hb[0] + mt * 64 * 256, 128, tid); CP_COMMIT();
    CP_WAIT(0); __syncthreads();
    mma_all();
    __syncthreads();
    stage_Bh(Bb, g_Wsum_h, nt8, tid);   // steady-state weights (synced via group_sync)
    epilogue(1);
    group_sync(mt, btarget); btarget += 8;
    // tail of step 0: prefetch A for step 1, stage+run predictor 0
    stage_Xs(1, 0); CP_COMMIT();
    stage_A(sbase + DOFF_A0, g_hb[1] + mt * 64 * 256, 0, tid);   CP_COMMIT();
    stage_A(sbase + DOFF_A1, g_hb[1] + mt * 64 * 256, 128, tid); CP_COMMIT();
    CP_WAIT(2); __syncthreads();
    predictor(0, 1);

    // ================= steady-state steps 1..127 =================
    for (int t = 1; t < LL; ++t) {
        const int ib = t & 1, ob = ib ^ 1;

        CP_WAIT(0); __syncthreads();   // A halves (staged in previous tail) ready
#pragma unroll
        for (int i = 0; i < 4; ++i)
#pragma unroll
            for (int j = 0; j < 4; ++j) C[i][j] = 0.f;
        mma_all();
        epilogue(ob);
        group_sync(mt, btarget); btarget += 8;

        // tail: prefetch next A + predictor t (overlapped with cp.async)
        stage_Xs(ob, ib); CP_COMMIT();
        if (t < LL - 1) {
            stage_A(sbase + DOFF_A0, g_hb[ob] + mt * 64 * 256, 0, tid);   CP_COMMIT();
            stage_A(sbase + DOFF_A1, g_hb[ob] + mt * 64 * 256, 128, tid); CP_COMMIT();
            CP_WAIT(2);
        } else {
            CP_WAIT(0);
        }
        __syncthreads();
        predictor(t, ob);
    }
}

// ---------------- fp16 tensor GEMM (3-way batched over blockIdx.z) -------------
__global__ void __launch_bounds__(256, 2)
gemm_h(const __half* __restrict__ Aa, const __half* __restrict__ Ab_, const __half* __restrict__ Ac,
       const __half* __restrict__ Wa, const __half* __restrict__ Wb, const __half* __restrict__ Wc,
       const float* __restrict__ ba, const float* __restrict__ bb, const float* __restrict__ bc,
       __half* Cha, __half* Chb, __half* Chc,
       float* Cfa, float* Cfb, float* Cfc,
       int N, int K, int act) {
    __shared__ __half As[64 * 72];
    __shared__ __half Bs[64 * 72];
    const int z = blockIdx.z;
    const __half* A = (z == 0) ? Aa : (z == 1) ? Ab_ : Ac;
    const __half* W = (z == 0) ? Wa : (z == 1) ? Wb : Wc;
    const float* bias = (z == 0) ? ba : (z == 1) ? bb : bc;
    __half* Ch = (z == 0) ? Cha : (z == 1) ? Chb : Chc;
    float* Cf = (z == 0) ? Cfa : (z == 1) ? Cfb : Cfc;

    const int tid = threadIdx.x;
    const int wid = tid >> 5, lane = tid & 31;
    const int gid = lane >> 2, tig = lane & 3;
    const int wm = wid >> 2, wn = wid & 3;       // 2M x 4N warp grid, warp 32x16
    const int m0 = blockIdx.y * 64, n0 = blockIdx.x * 64;

    const uint32_t sA = smem_u32(As), sB = smem_u32(Bs);
    const uint32_t aFrag = sA + (uint32_t)(((wm * 32 + (lane & 15)) * 72 + (lane >> 4) * 8) * 2);
    const uint32_t bFrag = sB + (uint32_t)(((wn * 16 + (lane >> 4) * 8 + (lane & 7)) * 72 +
                                            ((lane >> 3) & 1) * 8) * 2);

    float C[4][4];
#pragma unroll
    for (int i = 0; i < 4; ++i)
#pragma unroll
        for (int j = 0; j < 4; ++j) C[i][j] = 0.f;

    for (int kk = 0; kk < K; kk += 64) {
        {
            int r = tid >> 2, cb = (tid & 3) * 16;
            *reinterpret_cast<uint4*>(As + r * 72 + cb) =
                *reinterpret_cast<const uint4*>(A + (m0 + r) * K + kk + cb);
            *reinterpret_cast<uint4*>(As + r * 72 + cb + 8) =
                *reinterpret_cast<const uint4*>(A + (m0 + r) * K + kk + cb + 8);
            *reinterpret_cast<uint4*>(Bs + r * 72 + cb) =
                *reinterpret_cast<const uint4*>(W + (n0 + r) * K + kk + cb);
            *reinterpret_cast<uint4*>(Bs + r * 72 + cb + 8) =
                *reinterpret_cast<const uint4*>(W + (n0 + r) * K + kk + cb + 8);
        }
        __syncthreads();
#pragma unroll
        for (int ks = 0; ks < 4; ++ks) {
            uint32_t a0[4], a1[4], b[4];
            ldsm4(aFrag + ks * 32, a0);
            ldsm4(aFrag + 16 * 72 * 2 + ks * 32, a1);
            ldsm4(bFrag + ks * 32, b);
            mma16(C[0], a0, b[0], b[1]);
            mma16(C[1], a0, b[2], b[3]);
            mma16(C[2], a1, b[0], b[1]);
            mma16(C[3], a1, b[2], b[3]);
        }
        __syncthreads();
    }

#pragma unroll
    for (int mf = 0; mf < 2; ++mf)
#pragma unroll
        for (int nf = 0; nf < 2; ++nf) {
            int r = m0 + wm * 32 + mf * 16 + gid;
            int c = n0 + wn * 16 + nf * 8 + 2 * tig;
            float b0 = bias[c], b1 = bias[c + 1];
            float v0 = C[mf * 2 + nf][0] + b0, v1 = C[mf * 2 + nf][1] + b1;
            float v2 = C[mf * 2 + nf][2] + b0, v3 = C[mf * 2 + nf][3] + b1;
            if (act) {
                v0 = v0 >= 0.f ? v0 : 0.2f * v0;
                v1 = v1 >= 0.f ? v1 : 0.2f * v1;
                v2 = v2 >= 0.f ? v2 : 0.2f * v2;
                v3 = v3 >= 0.f ? v3 : 0.2f * v3;
            }
            if (Ch) {
                *reinterpret_cast<__half2*>(Ch + r * N + c)       = __floats2half2_rn(v0, v1);
                *reinterpret_cast<__half2*>(Ch + (r + 8) * N + c) = __floats2half2_rn(v2, v3);
            } else {
                *reinterpret_cast<float2*>(Cf + r * N + c)       = make_float2(v0, v1);
                *reinterpret_cast<float2*>(Cf + (r + 8) * N + c) = make_float2(v2, v3);
            }
        }
}

// ---------------- init: convert weights/activations to fp16, sums, zeros -------
__global__ void init_kernel(const float* x, const float* W1, const float* W2, const float* W3,
                            const float* Wh1, const float* Wc1, const float* Wx1,
                            const float* Wh2, const float* Wc2, const float* Wx2,
                            const float* rWih, const float* rWhh,
                            const float* rbih, const float* rbhh,
                            const float* pbih, const float* pbhh) {
    const int i0 = blockIdx.x * blockDim.x + threadIdx.x;
    const int ns = gridDim.x * blockDim.x;
    for (int j = i0; j < 1024 * 256; j += ns) {
        float a = rWih[j], b = rWhh[j];
        g_Wsum_h[j] = __float2half(a + b);
        g_Wih_h[j]  = __float2half(a);
        g_Whh_h[j]  = __float2half(b);
    }
    for (int j = i0; j < 512 * 128; j += ns) g_W1h[j] = __float2half(W1[j]);
    for (int j = i0; j < 512 * 512; j += ns) {
        g_W2h[j]  = __float2half(W2[j]);
        g_W3h[j]  = __float2half(W3[j]);
        g_Wh1h[j] = __float2half(Wh1[j]);
        g_Wc1h[j] = __float2half(Wc1[j]);
        g_Wx1h[j] = __float2half(Wx1[j]);
    }
    for (int j = i0; j < 256 * 512; j += ns) {
        g_Wh2h[j] = __float2half(Wh2[j]);
        g_Wc2h[j] = __float2half(Wc2[j]);
        g_Wx2h[j] = __float2half(Wx2[j]);
    }
    for (int j = i0; j < BB * 128; j += ns) g_xh[j] = __float2half(x[j]);
    for (int j = i0; j < 1024; j += ns) g_rb[j] = rbih[j] + rbhh[j];
    for (int j = i0; j < 128; j += ns) g_pb[j] = pbih[j] + pbhh[j];
    for (int j = i0; j < BB * II; j += ns) {
        g_hp[0][j] = __float2half(0.f);
        g_hp[1][j] = __float2half(0.f);
    }
    for (int j = i0; j < 16 * 32; j += ns) g_gcnt[j] = 0;   // reset group barriers
}

// ---------------- epilogue: softmax over 31 channels + sigmoid on last ---------
__global__ void __launch_bounds__(256)
out_kernel(float* __restrict__ out) {
    int gw = (blockIdx.x * blockDim.x + threadIdx.x) >> 5;
    int lane = threadIdx.x & 31;
    if (gw >= BB * LL) return;
    float v = g_y[gw * 32 + lane];
    float sv = (lane < 31) ? v : -3.0e38f;
    float mx = sv;
#pragma unroll
    for (int o = 16; o; o >>= 1) mx = fmaxf(mx, __shfl_xor_sync(0xffffffffu, mx, o));
    float e = (lane < 31) ? expf(sv - mx) : 0.f;
    float s = e;
#pragma unroll
    for (int o = 16; o; o >>= 1) s += __shfl_xor_sync(0xffffffffu, s, o);
    float r = (lane < 31) ? (e / s) : (1.f / (1.f + expf(-v)));
    out[gw * 32 + lane] = r;
}

// ---------------- launcher ----------------------------------------------------
extern "C" void kernel_launch(void* const* d_in, const int* in_sizes, int n_in,
                              void* d_out, int out_size) {
    const float* x    = (const float*)d_in[0];
    const float* W1   = (const float*)d_in[1];  const float* b1  = (const float*)d_in[2];
    const float* W2   = (const float*)d_in[3];  const float* b2  = (const float*)d_in[4];
    const float* W3   = (const float*)d_in[5];  const float* b3  = (const float*)d_in[6];
    const float* Wh1  = (const float*)d_in[7];  const float* bh1 = (const float*)d_in[8];
    const float* Wh2  = (const float*)d_in[9];  const float* bh2 = (const float*)d_in[10];
    const float* Wc1  = (const float*)d_in[11]; const float* bc1 = (const float*)d_in[12];
    const float* Wc2  = (const float*)d_in[13]; const float* bc2 = (const float*)d_in[14];
    const float* Wx1  = (const float*)d_in[15]; const float* bx1 = (const float*)d_in[16];
    const float* Wx2  = (const float*)d_in[17]; const float* bx2 = (const float*)d_in[18];
    const float* rWih = (const float*)d_in[19]; const float* rWhh = (const float*)d_in[20];
    const float* rbih = (const float*)d_in[21]; const float* rbhh = (const float*)d_in[22];
    const float* pWih = (const float*)d_in[23]; const float* pWhh = (const float*)d_in[24];
    const float* pbih = (const float*)d_in[25]; const float* pbhh = (const float*)d_in[26];
    float* out = (float*)d_out;

    cudaFuncSetAttribute(decode_kernel, cudaFuncAttributeMaxDynamicSharedMemorySize, DEC_SMEM);

    init_kernel<<<512, 256>>>(x, W1, W2, W3, Wh1, Wc1, Wx1, Wh2, Wc2, Wx2,
                              rWih, rWhh, rbih, rbhh, pbih, pbhh);

    __half *t0h, *t1h, *xh, *hb0, *x0h, *th1, *tc1, *tx1;
    __half *w1, *w2, *w3, *wh1, *wc1, *wx1, *wh2, *wc2, *wx2;
    float* cbuf;
    cudaGetSymbolAddress((void**)&t0h, g_t0h);
    cudaGetSymbolAddress((void**)&t1h, g_t1h);
    cudaGetSymbolAddress((void**)&xh,  g_xh);
    cudaGetSymbolAddress((void**)&hb0, g_hb);     // g_hb[0]
    cudaGetSymbolAddress((void**)&x0h, g_x0h);
    cudaGetSymbolAddress((void**)&th1, g_th1);
    cudaGetSymbolAddress((void**)&tc1, g_tc1);
    cudaGetSymbolAddress((void**)&tx1, g_tx1);
    cudaGetSymbolAddress((void**)&cbuf, g_c);
    cudaGetSymbolAddress((void**)&w1,  g_W1h);
    cudaGetSymbolAddress((void**)&w2,  g_W2h);
    cudaGetSymbolAddress((void**)&w3,  g_W3h);
    cudaGetSymbolAddress((void**)&wh1, g_Wh1h);
    cudaGetSymbolAddress((void**)&wc1, g_Wc1h);
    cudaGetSymbolAddress((void**)&wx1, g_Wx1h);
    cudaGetSymbolAddress((void**)&wh2, g_Wh2h);
    cudaGetSymbolAddress((void**)&wc2, g_Wc2h);
    cudaGetSymbolAddress((void**)&wx2, g_Wx2h);

    dim3 blk(256);
    // L1..L3 (single, z=1)
    gemm_h<<<dim3(8, 16, 1), blk>>>(xh, xh, xh, w1, w1, w1, b1, b1, b1,
                                    t0h, NULL, NULL, NULL, NULL, NULL, 512, 128, 1);
    gemm_h<<<dim3(8, 16, 1), blk>>>(t0h, t0h, t0h, w2, w2, w2, b2, b2, b2,
                                    t1h, NULL, NULL, NULL, NULL, NULL, 512, 512, 1);
    gemm_h<<<dim3(8, 16, 1), blk>>>(t1h, t1h, t1h, w3, w3, w3, b3, b3, b3,
                                    t0h, NULL, NULL, NULL, NULL, NULL, 512, 512, 1);
    // heads layer 1 (batched z=3): t3 -> th1/tc1/tx1
    gemm_h<<<dim3(8, 16, 3), blk>>>(t0h, t0h, t0h, wh1, wc1, wx1, bh1, bc1, bx1,
                                    th1, tc1, tx1, NULL, NULL, NULL, 512, 512, 1);
    // heads layer 2 (batched z=3): -> h0 (fp16), c0 (fp32), x0 (fp16)
    gemm_h<<<dim3(4, 16, 3), blk>>>(th1, tc1, tx1, wh2, wc2, wx2, bh2, bc2, bx2,
                                    hb0, NULL, x0h, NULL, cbuf, NULL, 256, 512, 0);

    decode_kernel<<<NBLK, NTHR, DEC_SMEM>>>(pWih, pWhh);

    out_kernel<<<(BB * LL) / 8, 256>>>(out);
}

// round 14
// speedup vs baseline: 7.8281x; 1.1773x over previous
#include <cuda_runtime.h>
#include <cuda_fp16.h>
#include <math.h>
#include <stdint.h>

// Problem dims
#define BB 1024
#define HH 256
#define II 32
#define LL 128

#define NBLK 128
#define NTHR 512

// ---------------- device scratch ----------------------------------------------
__device__ __align__(16) __half g_Wsum_h[1024 * 256];  // fp16(rWih + rWhh)
__device__ __align__(16) __half g_Wih_h[1024 * 256];
__device__ __align__(16) __half g_Whh_h[1024 * 256];
__device__ __align__(16) __half g_hb[2][BB * HH];      // decode hidden ping-pong (fp16)
__device__ __align__(16) float  g_c[BB * HH];          // decode cell init (fp32)
__device__ __align__(16) __half g_x0h[BB * HH];
__device__ __align__(16) __half g_hp[2][BB * II];      // predictor hidden ping-pong
__device__ __align__(16) float  g_y[BB * LL * II];     // predictor outputs (fp32)
__device__ float g_rb[1024];
__device__ float g_pb[128];
__device__ unsigned g_gcnt[16 * 32];                   // decode group barriers (8 CTAs)
__device__ unsigned g_pcnt[32 * 32];                   // predictor group barriers (4 CTAs)
// fp16 activations + weights for the MLP front
__device__ __align__(16) __half g_xh[BB * 128];
__device__ __align__(16) __half g_t0h[BB * 512];
__device__ __align__(16) __half g_t1h[BB * 512];
__device__ __align__(16) __half g_th1[BB * 512];
__device__ __align__(16) __half g_tc1[BB * 512];
__device__ __align__(16) __half g_tx1[BB * 512];
__device__ __align__(16) __half g_W1h[512 * 128];
__device__ __align__(16) __half g_W2h[512 * 512];
__device__ __align__(16) __half g_W3h[512 * 512];
__device__ __align__(16) __half g_Wh1h[512 * 512];
__device__ __align__(16) __half g_Wc1h[512 * 512];
__device__ __align__(16) __half g_Wx1h[512 * 512];
__device__ __align__(16) __half g_Wh2h[256 * 512];
__device__ __align__(16) __half g_Wc2h[256 * 512];
__device__ __align__(16) __half g_Wx2h[256 * 512];

// ---------------- helpers ------------------------------------------------------
__device__ __forceinline__ uint32_t smem_u32(const void* p) {
    uint32_t a;
    asm("{ .reg .u64 t; cvta.to.shared.u64 t, %1; cvt.u32.u64 %0, t; }" : "=r"(a) : "l"(p));
    return a;
}
__device__ __forceinline__ float fsigm(float x) {
    return __fdividef(1.f, 1.f + __expf(-x));
}
__device__ __forceinline__ float ftanh(float x) {
    return 1.f - __fdividef(2.f, __expf(2.f * x) + 1.f);
}
__device__ __forceinline__ unsigned ldcg_u32(const unsigned* p) {
    unsigned v;
    asm volatile("ld.global.cg.u32 %0, [%1];" : "=r"(v) : "l"(p) : "memory");
    return v;
}
__device__ __forceinline__ void barx(int id) {
    asm volatile("bar.sync %0, 256;" :: "r"(id) : "memory");
}

// m16n8k16 fp16 mma, fp32 accum
__device__ __forceinline__ void mma16(float* c, const uint32_t* a, uint32_t b0, uint32_t b1) {
    asm volatile("mma.sync.aligned.m16n8k16.row.col.f32.f16.f16.f32 "
                 "{%0,%1,%2,%3}, {%4,%5,%6,%7}, {%8,%9}, {%0,%1,%2,%3};"
                 : "+f"(c[0]), "+f"(c[1]), "+f"(c[2]), "+f"(c[3])
                 : "r"(a[0]), "r"(a[1]), "r"(a[2]), "r"(a[3]), "r"(b0), "r"(b1));
}
__device__ __forceinline__ void ldsm4(uint32_t addr, uint32_t* r) {
    asm volatile("ldmatrix.sync.aligned.m8n8.x4.shared.b16 {%0,%1,%2,%3}, [%4];"
                 : "=r"(r[0]), "=r"(r[1]), "=r"(r[2]), "=r"(r[3]) : "r"(addr));
}
__device__ __forceinline__ void cp16(uint32_t d, const void* s) {
    asm volatile("cp.async.cg.shared.global [%0], [%1], 16;" :: "r"(d), "l"(s));
}
#define CP_COMMIT() asm volatile("cp.async.commit_group;" ::: "memory")
#define CP_WAIT(n)  asm volatile("cp.async.wait_group %0;" :: "n"(n) : "memory")

// ---------------- decode SMEM layout (byte offsets; all regions disjoint) ------
#define DOFF_B    0          // [128][264]h weights (67584)
#define DOFF_A0   67584      // [64][136]h A half 0 (17408)
#define DOFF_A1   84992      // [64][136]h A half 1 (17408)
#define DOFF_G    102400     // [64][132]f gate exchange (33792)
#define DOFF_XS   136192     // [32][296]h predictor X (18944)
#define DOFF_P    155136     // [4][32][8]f predictor exchange (4096)
#define DOFF_BD   159232     // 128 f decode bias
#define DOFF_BP   159744     // 32 f predictor bias
#define DEC_SMEM  159872

// stage B with 256 threads (decode group): 128 rows x 256 halves, stride 264
__device__ __forceinline__ void stage_Bh(__half* Bb, const __half* __restrict__ W,
                                         int nt8, int tid) {
#pragma unroll
    for (int i = 0; i < 16; ++i) {
        int e = tid + i * 256;
        int n = e >> 5, cb = (e & 31) * 8;
        int grow = (n >> 5) * 256 + nt8 * 32 + (n & 31);
        *reinterpret_cast<uint4*>(Bb + n * 264 + cb) =
            *reinterpret_cast<const uint4*>(W + grow * 256 + cb);
    }
}
// stage A half with 256 threads: 64 rows x 128 halves (src row stride 256)
__device__ __forceinline__ void stage_A(uint32_t Abase, const __half* src, int kc0, int tid) {
#pragma unroll
    for (int i = 0; i < 4; ++i) {
        int e = tid + i * 256;
        int r = e >> 4, cb = (e & 15) * 8;
        cp16(Abase + (uint32_t)(r * 136 + cb) * 2u, src + r * 256 + kc0 + cb);
    }
}

// ---------------- persistent decode + predictor kernel (warp-specialized) ------
__global__ void __launch_bounds__(NTHR, 1)
decode_kernel(const float* __restrict__ pWih, const float* __restrict__ pWhh) {
    extern __shared__ char sm[];
    __shared__ volatile int s_step;
    const uint32_t sbase = smem_u32(sm);
    __half* Bb = (__half*)(sm + DOFF_B);
    float* G  = (float*)(sm + DOFF_G);
    float* P  = (float*)(sm + DOFF_P);
    float* biasD = (float*)(sm + DOFF_BD);
    float* biasP = (float*)(sm + DOFF_BP);

    const int bid = blockIdx.x;
    const int tid = threadIdx.x;
    const int wid = tid >> 5, lane = tid & 31;
    const int gid = lane >> 2, tig = lane & 3;
    // decode: 16 M-tiles(64 rows) x 8 col-tiles(32 hcols x 4 gates)
    const int mt = bid >> 3, nt8 = bid & 7;
    // predictor role: rows pm*32 within the decode group (group = mt)
    const int pm = mt * 2 + (nt8 >> 2), pic = nt8 & 3;

    if (tid == 0) s_step = -1;
    if (tid < 128) biasD[tid] = g_rb[(tid >> 5) * 256 + nt8 * 32 + (tid & 31)];
    if (tid < 32)  biasP[tid] = g_pb[(tid >> 3) * 32 + pic * 8 + (tid & 7)];

    // ============ predictor-group persistent state (warps 8-15) ============
    uint32_t pB[18][2];
    if (wid >= 8) {
        const int png = (wid - 8) & 3;
        const int prow = png * 32 + pic * 8 + gid;
#pragma unroll
        for (int ks = 0; ks < 18; ++ks) {
#pragma unroll
            for (int hh = 0; hh < 2; ++hh) {
                int k = ks * 16 + 2 * tig + hh * 8;
                float v0 = (k < 256) ? pWih[prow * 256 + k] : pWhh[prow * 32 + (k - 256)];
                float v1 = (k + 1 < 256) ? pWih[prow * 256 + k + 1] : pWhh[prow * 32 + (k + 1 - 256)];
                __half2 h2 = __floats2half2_rn(v0, v1);
                pB[ks][hh] = *reinterpret_cast<uint32_t*>(&h2);
            }
        }
    }

    // ============ decode-group persistent state (warps 0-7) ============
    float creg[8];
    if (tid < 256) {
        const int rr = tid >> 2, hb_ = (tid & 3) * 8;
        const float* cp_ = g_c + (mt * 64 + rr) * 256 + nt8 * 32 + hb_;
        float4 c0 = *reinterpret_cast<const float4*>(cp_);
        float4 c1 = *reinterpret_cast<const float4*>(cp_ + 4);
        creg[0] = c0.x; creg[1] = c0.y; creg[2] = c0.z; creg[3] = c0.w;
        creg[4] = c1.x; creg[5] = c1.y; creg[6] = c1.z; creg[7] = c1.w;
        stage_Bh(Bb, g_Wih_h, nt8, tid);   // step-0 first B
    }
    __syncthreads();
    // ------- no __syncthreads below this line (groups diverge) -------

    if (wid < 8) {
        // ======================= DECODE ENGINE (warps 0-7) =======================
        const int wm = wid >> 2, wn = wid & 3;    // 2M x 4N, warp tile 32x32
        const int rr = tid >> 2, hb_ = (tid & 3) * 8;
        const uint32_t aFragOff = (uint32_t)(((lane & 15) * 136 + (lane >> 4) * 8) * 2);
        const uint32_t aA0 = sbase + DOFF_A0 + (uint32_t)(wm * 32 * 136 * 2) + aFragOff;
        const uint32_t aA1 = sbase + DOFF_A1 + (uint32_t)(wm * 32 * 136 * 2) + aFragOff;
        const uint32_t aB  = sbase + DOFF_B +
            (uint32_t)(((wn * 32 + (lane >> 4) * 8 + (lane & 7)) * 264 + ((lane >> 3) & 1) * 8) * 2);

        float C[8][4];

        auto mma_all = [&]() {
#pragma unroll
            for (int h = 0; h < 2; ++h) {
                const uint32_t ab = h ? aA1 : aA0;
                const uint32_t bb = aB + (uint32_t)(h * 256);
#pragma unroll
                for (int ks = 0; ks < 8; ++ks) {
                    uint32_t a0[4], a1[4], b0[4], b1[4];
                    ldsm4(ab + ks * 32, a0);
                    ldsm4(ab + 4352 + ks * 32, a1);        // +16 rows * 136h * 2B
                    ldsm4(bb + ks * 32, b0);
                    ldsm4(bb + 8448 + ks * 32, b1);        // +16 B-rows * 264h * 2B
                    mma16(C[0], a0, b0[0], b0[1]);
                    mma16(C[1], a0, b0[2], b0[3]);
                    mma16(C[2], a0, b1[0], b1[1]);
                    mma16(C[3], a0, b1[2], b1[3]);
                    mma16(C[4], a1, b0[0], b0[1]);
                    mma16(C[5], a1, b0[2], b0[3]);
                    mma16(C[6], a1, b1[0], b1[1]);
                    mma16(C[7], a1, b1[2], b1[3]);
                }
            }
        };

        auto epilogue = [&](int ob) {
#pragma unroll
            for (int mf = 0; mf < 2; ++mf)
#pragma unroll
                for (int nf = 0; nf < 4; ++nf) {
                    int r = wm * 32 + mf * 16 + gid;
                    int cl = wn * 32 + nf * 8 + 2 * tig;
                    *reinterpret_cast<float2*>(&G[r * 132 + cl]) =
                        make_float2(C[mf * 4 + nf][0], C[mf * 4 + nf][1]);
                    *reinterpret_cast<float2*>(&G[(r + 8) * 132 + cl]) =
                        make_float2(C[mf * 4 + nf][2], C[mf * 4 + nf][3]);
                }
            barx(1);
            float4 gi0 = *reinterpret_cast<const float4*>(&G[rr * 132 + hb_]);
            float4 gi1 = *reinterpret_cast<const float4*>(&G[rr * 132 + hb_ + 4]);
            float4 gf0 = *reinterpret_cast<const float4*>(&G[rr * 132 + 32 + hb_]);
            float4 gf1 = *reinterpret_cast<const float4*>(&G[rr * 132 + 32 + hb_ + 4]);
            float4 gg0 = *reinterpret_cast<const float4*>(&G[rr * 132 + 64 + hb_]);
            float4 gg1 = *reinterpret_cast<const float4*>(&G[rr * 132 + 64 + hb_ + 4]);
            float4 go0 = *reinterpret_cast<const float4*>(&G[rr * 132 + 96 + hb_]);
            float4 go1 = *reinterpret_cast<const float4*>(&G[rr * 132 + 96 + hb_ + 4]);
            float iv[8] = {gi0.x, gi0.y, gi0.z, gi0.w, gi1.x, gi1.y, gi1.z, gi1.w};
            float fv[8] = {gf0.x, gf0.y, gf0.z, gf0.w, gf1.x, gf1.y, gf1.z, gf1.w};
            float gv[8] = {gg0.x, gg0.y, gg0.z, gg0.w, gg1.x, gg1.y, gg1.z, gg1.w};
            float ov[8] = {go0.x, go0.y, go0.z, go0.w, go1.x, go1.y, go1.z, go1.w};
            __half hv[8];
#pragma unroll
            for (int j = 0; j < 8; ++j) {
                int hcl = hb_ + j;
                float ii = iv[j] + biasD[hcl];
                float ff = fv[j] + biasD[32 + hcl];
                float gg = gv[j] + biasD[64 + hcl];
                float oo = ov[j] + biasD[96 + hcl];
                float cn = fsigm(ff) * creg[j] + fsigm(ii) * ftanh(gg);
                creg[j] = cn;
                hv[j] = __float2half(fsigm(oo) * ftanh(cn));
            }
            *reinterpret_cast<uint4*>(g_hb[ob] + (mt * 64 + rr) * 256 + nt8 * 32 + hb_) =
                *reinterpret_cast<uint4*>(hv);
        };

        auto dec_barrier = [&](int t) {
            barx(1);                                  // all h stores in group order
            if (tid == 0) {
                unsigned* cnt = &g_gcnt[mt * 32];
                __threadfence();
                atomicAdd(cnt, 1u);
                unsigned target = 8u * (unsigned)(t + 1);
                while (ldcg_u32(cnt) < target) { }
                __threadfence();
                s_step = t;
            }
            barx(1);
        };

        // ---------------- step 0 (two B matrices) ----------------
#pragma unroll
        for (int i = 0; i < 8; ++i)
#pragma unroll
            for (int j = 0; j < 4; ++j) C[i][j] = 0.f;
        stage_A(sbase + DOFF_A0, g_x0h + mt * 64 * 256, 0, tid);
        stage_A(sbase + DOFF_A1, g_x0h + mt * 64 * 256, 128, tid);
        CP_COMMIT(); CP_WAIT(0); barx(1);
        mma_all();
        barx(1);
        stage_Bh(Bb, g_Whh_h, nt8, tid); barx(1);
        stage_A(sbase + DOFF_A0, g_hb[0] + mt * 64 * 256, 0, tid);
        stage_A(sbase + DOFF_A1, g_hb[0] + mt * 64 * 256, 128, tid);
        CP_COMMIT(); CP_WAIT(0); barx(1);
        mma_all();
        barx(1);
        stage_Bh(Bb, g_Wsum_h, nt8, tid);    // steady-state B (reads resume after bars)
        epilogue(1);
        dec_barrier(0);
        stage_A(sbase + DOFF_A0, g_hb[1] + mt * 64 * 256, 0, tid);
        stage_A(sbase + DOFF_A1, g_hb[1] + mt * 64 * 256, 128, tid);
        CP_COMMIT();

        // ---------------- steady state t = 1..127 ----------------
        for (int t = 1; t < LL; ++t) {
            const int ob = (t & 1) ^ 1;
            CP_WAIT(0); barx(1);
#pragma unroll
            for (int i = 0; i < 8; ++i)
#pragma unroll
                for (int j = 0; j < 4; ++j) C[i][j] = 0.f;
            mma_all();
            epilogue(ob);
            dec_barrier(t);
            if (t < LL - 1) {
                stage_A(sbase + DOFF_A0, g_hb[ob] + mt * 64 * 256, 0, tid);
                stage_A(sbase + DOFF_A1, g_hb[ob] + mt * 64 * 256, 128, tid);
                CP_COMMIT();
            }
        }
    } else {
        // ===================== PREDICTOR ENGINE (warps 8-15) =====================
        const int pt = tid - 256;
        const int pwid = wid - 8;
        const int pmt = (pwid >> 2) & 1, png = pwid & 3;
        const uint32_t xA = sbase + DOFF_XS +
            (uint32_t)(((pmt * 16 + (lane & 15)) * 296 + (lane >> 4) * 8) * 2);
        float cp_reg = 0.f;

        for (int t = 0; t < LL; ++t) {
            const int ib = t & 1, ob = ib ^ 1;

            if (pt == 0) {
                while (s_step < t) { }                        // decode published h[t]
                if (t > 0) {                                  // sibling hp[t-1] done
                    unsigned* pc = &g_pcnt[pm * 32];
                    unsigned target = 4u * (unsigned)t;
                    while (ldcg_u32(pc) < target) { }
                }
                __threadfence();
            }
            barx(2);

            // stage X = [h[ob] rows pm*32..+32 (256) | hp[ib] (32)]
#pragma unroll
            for (int i = 0; i < 5; ++i) {
                int e = pt + i * 256;
                if (e < 1152) {
                    int r = e / 36, ch = e % 36;
                    const __half* src = (ch < 32)
                        ? (g_hb[ob] + (pm * 32 + r) * 256 + ch * 8)
                        : (g_hp[ib] + (pm * 32 + r) * 32 + (ch - 32) * 8);
                    cp16(sbase + DOFF_XS + (uint32_t)(r * 296 + ch * 8) * 2u, src);
                }
            }
            CP_COMMIT(); CP_WAIT(0); barx(2);

            {
                float pc[4] = {0.f, 0.f, 0.f, 0.f};
#pragma unroll
                for (int ks = 0; ks < 18; ++ks) {
                    uint32_t a[4];
                    ldsm4(xA + ks * 32, a);
                    mma16(pc, a, pB[ks][0], pB[ks][1]);
                }
                int ml = pmt * 16 + gid;
                *reinterpret_cast<float2*>(&P[(png * 32 + ml) * 8 + 2 * tig]) =
                    make_float2(pc[0], pc[1]);
                *reinterpret_cast<float2*>(&P[(png * 32 + ml + 8) * 8 + 2 * tig]) =
                    make_float2(pc[2], pc[3]);
            }
            barx(2);
            {
                int ml = pt >> 3, ic = pt & 7;
                float iv = P[(0  + ml) * 8 + ic] + biasP[ic];
                float fv = P[(32 + ml) * 8 + ic] + biasP[8 + ic];
                float gv = P[(64 + ml) * 8 + ic] + biasP[16 + ic];
                float ov = P[(96 + ml) * 8 + ic] + biasP[24 + ic];
                float cn = fsigm(fv) * cp_reg + fsigm(iv) * ftanh(gv);
                cp_reg = cn;
                float hn = fsigm(ov) * ftanh(cn);
                int m = pm * 32 + ml, icol = pic * 8 + ic;
                g_hp[ob][m * 32 + icol] = __float2half(hn);
                g_y[(m * LL + t) * II + icol] = hn;
            }
            barx(2);                                  // all hp/y stores ordered
            if (pt == 0) {
                __threadfence();
                atomicAdd(&g_pcnt[pm * 32], 1u);
            }
        }
    }
}

// ---------------- fp16 tensor GEMM (3-way batched over blockIdx.z) -------------
__global__ void __launch_bounds__(256, 2)
gemm_h(const __half* __restrict__ Aa, const __half* __restrict__ Ab_, const __half* __restrict__ Ac,
       const __half* __restrict__ Wa, const __half* __restrict__ Wb, const __half* __restrict__ Wc,
       const float* __restrict__ ba, const float* __restrict__ bb, const float* __restrict__ bc,
       __half* Cha, __half* Chb, __half* Chc,
       float* Cfa, float* Cfb, float* Cfc,
       int N, int K, int act) {
    __shared__ __half As[64 * 72];
    __shared__ __half Bs[64 * 72];
    const int z = blockIdx.z;
    const __half* A = (z == 0) ? Aa : (z == 1) ? Ab_ : Ac;
    const __half* W = (z == 0) ? Wa : (z == 1) ? Wb : Wc;
    const float* bias = (z == 0) ? ba : (z == 1) ? bb : bc;
    __half* Ch = (z == 0) ? Cha : (z == 1) ? Chb : Chc;
    float* Cf = (z == 0) ? Cfa : (z == 1) ? Cfb : Cfc;

    const int tid = threadIdx.x;
    const int wid = tid >> 5, lane = tid & 31;
    const int gid = lane >> 2, tig = lane & 3;
    const int wm = wid >> 2, wn = wid & 3;
    const int m0 = blockIdx.y * 64, n0 = blockIdx.x * 64;

    const uint32_t sA = smem_u32(As), sB = smem_u32(Bs);
    const uint32_t aFrag = sA + (uint32_t)(((wm * 32 + (lane & 15)) * 72 + (lane >> 4) * 8) * 2);
    const uint32_t bFrag = sB + (uint32_t)(((wn * 16 + (lane >> 4) * 8 + (lane & 7)) * 72 +
                                            ((lane >> 3) & 1) * 8) * 2);

    float C[4][4];
#pragma unroll
    for (int i = 0; i < 4; ++i)
#pragma unroll
        for (int j = 0; j < 4; ++j) C[i][j] = 0.f;

    for (int kk = 0; kk < K; kk += 64) {
        {
            int r = tid >> 2, cb = (tid & 3) * 16;
            *reinterpret_cast<uint4*>(As + r * 72 + cb) =
                *reinterpret_cast<const uint4*>(A + (m0 + r) * K + kk + cb);
            *reinterpret_cast<uint4*>(As + r * 72 + cb + 8) =
                *reinterpret_cast<const uint4*>(A + (m0 + r) * K + kk + cb + 8);
            *reinterpret_cast<uint4*>(Bs + r * 72 + cb) =
                *reinterpret_cast<const uint4*>(W + (n0 + r) * K + kk + cb);
            *reinterpret_cast<uint4*>(Bs + r * 72 + cb + 8) =
                *reinterpret_cast<const uint4*>(W + (n0 + r) * K + kk + cb + 8);
        }
        __syncthreads();
#pragma unroll
        for (int ks = 0; ks < 4; ++ks) {
            uint32_t a0[4], a1[4], b[4];
            ldsm4(aFrag + ks * 32, a0);
            ldsm4(aFrag + 16 * 72 * 2 + ks * 32, a1);
            ldsm4(bFrag + ks * 32, b);
            mma16(C[0], a0, b[0], b[1]);
            mma16(C[1], a0, b[2], b[3]);
            mma16(C[2], a1, b[0], b[1]);
            mma16(C[3], a1, b[2], b[3]);
        }
        __syncthreads();
    }

#pragma unroll
    for (int mf = 0; mf < 2; ++mf)
#pragma unroll
        for (int nf = 0; nf < 2; ++nf) {
            int r = m0 + wm * 32 + mf * 16 + gid;
            int c = n0 + wn * 16 + nf * 8 + 2 * tig;
            float b0 = bias[c], b1 = bias[c + 1];
            float v0 = C[mf * 2 + nf][0] + b0, v1 = C[mf * 2 + nf][1] + b1;
            float v2 = C[mf * 2 + nf][2] + b0, v3 = C[mf * 2 + nf][3] + b1;
            if (act) {
                v0 = v0 >= 0.f ? v0 : 0.2f * v0;
                v1 = v1 >= 0.f ? v1 : 0.2f * v1;
                v2 = v2 >= 0.f ? v2 : 0.2f * v2;
                v3 = v3 >= 0.f ? v3 : 0.2f * v3;
            }
            if (Ch) {
                *reinterpret_cast<__half2*>(Ch + r * N + c)       = __floats2half2_rn(v0, v1);
                *reinterpret_cast<__half2*>(Ch + (r + 8) * N + c) = __floats2half2_rn(v2, v3);
            } else {
                *reinterpret_cast<float2*>(Cf + r * N + c)       = make_float2(v0, v1);
                *reinterpret_cast<float2*>(Cf + (r + 8) * N + c) = make_float2(v2, v3);
            }
        }
}

// ---------------- init: convert weights/activations to fp16, sums, zeros -------
__global__ void init_kernel(const float* x, const float* W1, const float* W2, const float* W3,
                            const float* Wh1, const float* Wc1, const float* Wx1,
                            const float* Wh2, const float* Wc2, const float* Wx2,
                            const float* rWih, const float* rWhh,
                            const float* rbih, const float* rbhh,
                            const float* pbih, const float* pbhh) {
    const int i0 = blockIdx.x * blockDim.x + threadIdx.x;
    const int ns = gridDim.x * blockDim.x;
    for (int j = i0; j < 1024 * 256; j += ns) {
        float a = rWih[j], b = rWhh[j];
        g_Wsum_h[j] = __float2half(a + b);
        g_Wih_h[j]  = __float2half(a);
        g_Whh_h[j]  = __float2half(b);
    }
    for (int j = i0; j < 512 * 128; j += ns) g_W1h[j] = __float2half(W1[j]);
    for (int j = i0; j < 512 * 512; j += ns) {
        g_W2h[j]  = __float2half(W2[j]);
        g_W3h[j]  = __float2half(W3[j]);
        g_Wh1h[j] = __float2half(Wh1[j]);
        g_Wc1h[j] = __float2half(Wc1[j]);
        g_Wx1h[j] = __float2half(Wx1[j]);
    }
    for (int j = i0; j < 256 * 512; j += ns) {
        g_Wh2h[j] = __float2half(Wh2[j]);
        g_Wc2h[j] = __float2half(Wc2[j]);
        g_Wx2h[j] = __float2half(Wx2[j]);
    }
    for (int j = i0; j < BB * 128; j += ns) g_xh[j] = __float2half(x[j]);
    for (int j = i0; j < 1024; j += ns) g_rb[j] = rbih[j] + rbhh[j];
    for (int j = i0; j < 128; j += ns) g_pb[j] = pbih[j] + pbhh[j];
    for (int j = i0; j < BB * II; j += ns) {
        g_hp[0][j] = __float2half(0.f);
        g_hp[1][j] = __float2half(0.f);
    }
    for (int j = i0; j < 16 * 32; j += ns) g_gcnt[j] = 0;
    for (int j = i0; j < 32 * 32; j += ns) g_pcnt[j] = 0;
}

// ---------------- epilogue: softmax over 31 channels + sigmoid on last ---------
__global__ void __launch_bounds__(256)
out_kernel(float* __restrict__ out) {
    int gw = (blockIdx.x * blockDim.x + threadIdx.x) >> 5;
    int lane = threadIdx.x & 31;
    if (gw >= BB * LL) return;
    float v = g_y[gw * 32 + lane];
    float sv = (lane < 31) ? v : -3.0e38f;
    float mx = sv;
#pragma unroll
    for (int o = 16; o; o >>= 1) mx = fmaxf(mx, __shfl_xor_sync(0xffffffffu, mx, o));
    float e = (lane < 31) ? expf(sv - mx) : 0.f;
    float s = e;
#pragma unroll
    for (int o = 16; o; o >>= 1) s += __shfl_xor_sync(0xffffffffu, s, o);
    float r = (lane < 31) ? (e / s) : (1.f / (1.f + expf(-v)));
    out[gw * 32 + lane] = r;
}

// ---------------- launcher ----------------------------------------------------
extern "C" void kernel_launch(void* const* d_in, const int* in_sizes, int n_in,
                              void* d_out, int out_size) {
    const float* x    = (const float*)d_in[0];
    const float* W1   = (const float*)d_in[1];  const float* b1  = (const float*)d_in[2];
    const float* W2   = (const float*)d_in[3];  const float* b2  = (const float*)d_in[4];
    const float* W3   = (const float*)d_in[5];  const float* b3  = (const float*)d_in[6];
    const float* Wh1  = (const float*)d_in[7];  const float* bh1 = (const float*)d_in[8];
    const float* Wh2  = (const float*)d_in[9];  const float* bh2 = (const float*)d_in[10];
    const float* Wc1  = (const float*)d_in[11]; const float* bc1 = (const float*)d_in[12];
    const float* Wc2  = (const float*)d_in[13]; const float* bc2 = (const float*)d_in[14];
    const float* Wx1  = (const float*)d_in[15]; const float* bx1 = (const float*)d_in[16];
    const float* Wx2  = (const float*)d_in[17]; const float* bx2 = (const float*)d_in[18];
    const float* rWih = (const float*)d_in[19]; const float* rWhh = (const float*)d_in[20];
    const float* rbih = (const float*)d_in[21]; const float* rbhh = (const float*)d_in[22];
    const float* pWih = (const float*)d_in[23]; const float* pWhh = (const float*)d_in[24];
    const float* pbih = (const float*)d_in[25]; const float* pbhh = (const float*)d_in[26];
    float* out = (float*)d_out;

    cudaFuncSetAttribute(decode_kernel, cudaFuncAttributeMaxDynamicSharedMemorySize, DEC_SMEM);

    init_kernel<<<512, 256>>>(x, W1, W2, W3, Wh1, Wc1, Wx1, Wh2, Wc2, Wx2,
                              rWih, rWhh, rbih, rbhh, pbih, pbhh);

    __half *t0h, *t1h, *xh, *hb0, *x0h, *th1, *tc1, *tx1;
    __half *w1, *w2, *w3, *wh1, *wc1, *wx1, *wh2, *wc2, *wx2;
    float* cbuf;
    cudaGetSymbolAddress((void**)&t0h, g_t0h);
    cudaGetSymbolAddress((void**)&t1h, g_t1h);
    cudaGetSymbolAddress((void**)&xh,  g_xh);
    cudaGetSymbolAddress((void**)&hb0, g_hb);     // g_hb[0]
    cudaGetSymbolAddress((void**)&x0h, g_x0h);
    cudaGetSymbolAddress((void**)&th1, g_th1);
    cudaGetSymbolAddress((void**)&tc1, g_tc1);
    cudaGetSymbolAddress((void**)&tx1, g_tx1);
    cudaGetSymbolAddress((void**)&cbuf, g_c);
    cudaGetSymbolAddress((void**)&w1,  g_W1h);
    cudaGetSymbolAddress((void**)&w2,  g_W2h);
    cudaGetSymbolAddress((void**)&w3,  g_W3h);
    cudaGetSymbolAddress((void**)&wh1, g_Wh1h);
    cudaGetSymbolAddress((void**)&wc1, g_Wc1h);
    cudaGetSymbolAddress((void**)&wx1, g_Wx1h);
    cudaGetSymbolAddress((void**)&wh2, g_Wh2h);
    cudaGetSymbolAddress((void**)&wc2, g_Wc2h);
    cudaGetSymbolAddress((void**)&wx2, g_Wx2h);

    dim3 blk(256);
    gemm_h<<<dim3(8, 16, 1), blk>>>(xh, xh, xh, w1, w1, w1, b1, b1, b1,
                                    t0h, NULL, NULL, NULL, NULL, NULL, 512, 128, 1);
    gemm_h<<<dim3(8, 16, 1), blk>>>(t0h, t0h, t0h, w2, w2, w2, b2, b2, b2,
                                    t1h, NULL, NULL, NULL, NULL, NULL, 512, 512, 1);
    gemm_h<<<dim3(8, 16, 1), blk>>>(t1h, t1h, t1h, w3, w3, w3, b3, b3, b3,
                                    t0h, NULL, NULL, NULL, NULL, NULL, 512, 512, 1);
    gemm_h<<<dim3(8, 16, 3), blk>>>(t0h, t0h, t0h, wh1, wc1, wx1, bh1, bc1, bx1,
                                    th1, tc1, tx1, NULL, NULL, NULL, 512, 512, 1);
    gemm_h<<<dim3(4, 16, 3), blk>>>(th1, tc1, tx1, wh2, wc2, wx2, bh2, bc2, bx2,
                                    hb0, NULL, x0h, NULL, cbuf, NULL, 256, 512, 0);

    decode_kernel<<<NBLK, NTHR, DEC_SMEM>>>(pWih, pWhh);

    out_kernel<<<(BB * LL) / 8, 256>>>(out);
}